// round 1
// baseline (speedup 1.0000x reference)
#include <cuda_runtime.h>
#include <math.h>

// ---------------------------------------------------------------------------
// Problem constants (shapes are fixed by the dataset)
// ---------------------------------------------------------------------------
#define NROWS 65536
#define DIM   256
#define H1    512
#define H2    2048

// ---------------------------------------------------------------------------
// Device scratch (allocation-free rule: __device__ globals)
// ---------------------------------------------------------------------------
__device__ __align__(16) float g_partS[256 * 256];
__device__ __align__(16) float g_partQ[256 * 256];
__device__ __align__(16) float g_scale[DIM];
__device__ __align__(16) float g_shift[DIM];
__device__ __align__(16) float g_xn[(size_t)NROWS * DIM];    //  64 MB
__device__ __align__(16) float g_h1[(size_t)NROWS * H1];     // 128 MB
__device__ __align__(16) float g_h2[(size_t)NROWS * H2];     // 512 MB

// ---------------------------------------------------------------------------
// K0: per-column partial sums. 256 blocks x 256 threads.
// Block b reduces rows [b*256, (b+1)*256); thread t owns column t.
// ---------------------------------------------------------------------------
__global__ void bn_partial(const float* __restrict__ x) {
    int c = threadIdx.x;
    int b = blockIdx.x;
    const float* xp = x + (size_t)b * 256 * DIM + c;
    float s = 0.f, q = 0.f;
#pragma unroll 8
    for (int r = 0; r < 256; r++) {
        float v = xp[(size_t)r * DIM];
        s += v;
        q += v * v;
    }
    g_partS[b * 256 + c] = s;
    g_partQ[b * 256 + c] = q;
}

// ---------------------------------------------------------------------------
// K1: finalize mean/var -> scale/shift. 1 block x 256 threads.
// ---------------------------------------------------------------------------
__global__ void bn_final(const float* __restrict__ gamma,
                         const float* __restrict__ beta) {
    int c = threadIdx.x;
    float s = 0.f, q = 0.f;
#pragma unroll 4
    for (int b = 0; b < 256; b++) {
        s += g_partS[b * 256 + c];
        q += g_partQ[b * 256 + c];
    }
    const float inv = 1.0f / (float)NROWS;
    float mu  = s * inv;
    float var = q * inv - mu * mu;
    float sc  = gamma[c] * rsqrtf(var + 1e-5f);
    g_scale[c] = sc;
    g_shift[c] = beta[c] - mu * sc;
}

// ---------------------------------------------------------------------------
// K2: xn = x*scale+shift -> scratch;  raw_feats = tanh(xn) -> d_out tail.
// One float4 per thread, 16384 blocks x 256 threads (exactly N*D/4 elements).
// ---------------------------------------------------------------------------
__global__ void bn_norm_tanh(const float4* __restrict__ x4,
                             float4* __restrict__ raw4,
                             float4* __restrict__ xn4) {
    int i = blockIdx.x * blockDim.x + threadIdx.x;
    int c0 = (i * 4) & (DIM - 1);
    float4 v = x4[i];
    float4 xn;
    xn.x = v.x * g_scale[c0 + 0] + g_shift[c0 + 0];
    xn.y = v.y * g_scale[c0 + 1] + g_shift[c0 + 1];
    xn.z = v.z * g_scale[c0 + 2] + g_shift[c0 + 2];
    xn.w = v.w * g_scale[c0 + 3] + g_shift[c0 + 3];
    xn4[i] = xn;
    float4 t;
    t.x = tanhf(xn.x);
    t.y = tanhf(xn.y);
    t.z = tanhf(xn.z);
    t.w = tanhf(xn.w);
    raw4[i] = t;
}

// ---------------------------------------------------------------------------
// GEMM: C[M,N] = A[M,K] @ W[N,K]^T + bias (optional tanh).
// tf32 via mma.sync.m16n8k8, fp32 accumulate.
// Block tile 128x128, BK=32, 256 threads (8 warps, 4x2 grid of 32x64 warp
// tiles), double-buffered smem with register prefetch.
// ---------------------------------------------------------------------------
__device__ __forceinline__ unsigned f2tf(float f) {
    unsigned u;
    asm("cvt.rna.tf32.f32 %0, %1;" : "=r"(u) : "f"(f));
    return u;
}

#define SMSTRIDE 36           // 32 + 4 pad -> conflict-free fragment loads
#define SMTILE  (128 * SMSTRIDE)

template <bool TANH>
__global__ __launch_bounds__(256)
void gemm_tn(const float* __restrict__ A, const float* __restrict__ W,
             const float* __restrict__ bias, float* __restrict__ C,
             int M, int N, int K) {
    extern __shared__ unsigned sm[];
    unsigned* As = sm;                 // [2][128][36]
    unsigned* Bs = sm + 2 * SMTILE;    // [2][128][36]

    const int tid  = threadIdx.x;
    const int lane = tid & 31;
    const int g    = lane >> 2;   // 0..7
    const int tg   = lane & 3;    // 0..3
    const int warp = tid >> 5;
    const int mo   = (warp & 3) * 32;
    const int no   = (warp >> 2) * 64;

    const size_t rowBase = (size_t)blockIdx.y * 128;
    const size_t colBase = (size_t)blockIdx.x * 128;

    const float* Ag = A + rowBase * (size_t)K;
    const float* Wg = W + colBase * (size_t)K;

    const int r0 = tid >> 3;          // 0..31
    const int c0 = (tid & 7) << 2;    // 0,4,...,28

    float4 pa[4], pb[4];

    float acc[2][8][4];
#pragma unroll
    for (int mi = 0; mi < 2; mi++)
#pragma unroll
        for (int ni = 0; ni < 8; ni++)
#pragma unroll
            for (int k = 0; k < 4; k++) acc[mi][ni][k] = 0.f;

    const int T = K >> 5;

    // --- prologue: fetch + store tile 0 ---
    {
        size_t k0 = (size_t)c0;
#pragma unroll
        for (int s = 0; s < 4; s++) {
            pa[s] = *(const float4*)(Ag + (size_t)(r0 + s * 32) * K + k0);
            pb[s] = *(const float4*)(Wg + (size_t)(r0 + s * 32) * K + k0);
        }
#pragma unroll
        for (int s = 0; s < 4; s++) {
            unsigned* da = As + (r0 + s * 32) * SMSTRIDE + c0;
            da[0] = f2tf(pa[s].x); da[1] = f2tf(pa[s].y);
            da[2] = f2tf(pa[s].z); da[3] = f2tf(pa[s].w);
            unsigned* db = Bs + (r0 + s * 32) * SMSTRIDE + c0;
            db[0] = f2tf(pb[s].x); db[1] = f2tf(pb[s].y);
            db[2] = f2tf(pb[s].z); db[3] = f2tf(pb[s].w);
        }
    }
    __syncthreads();

    for (int kt = 0; kt < T; kt++) {
        const int cur = kt & 1;
        // prefetch next tile into registers (overlaps with compute)
        if (kt + 1 < T) {
            size_t k0 = (size_t)(kt + 1) * 32 + c0;
#pragma unroll
            for (int s = 0; s < 4; s++) {
                pa[s] = *(const float4*)(Ag + (size_t)(r0 + s * 32) * K + k0);
                pb[s] = *(const float4*)(Wg + (size_t)(r0 + s * 32) * K + k0);
            }
        }

        const unsigned* Ab = As + cur * SMTILE;
        const unsigned* Bb = Bs + cur * SMTILE;
#pragma unroll
        for (int kk = 0; kk < 32; kk += 8) {
            unsigned a[2][4], b[8][2];
#pragma unroll
            for (int mi = 0; mi < 2; mi++) {
                int rr = mo + mi * 16;
                a[mi][0] = Ab[(rr + g)     * SMSTRIDE + kk + tg];
                a[mi][1] = Ab[(rr + g + 8) * SMSTRIDE + kk + tg];
                a[mi][2] = Ab[(rr + g)     * SMSTRIDE + kk + tg + 4];
                a[mi][3] = Ab[(rr + g + 8) * SMSTRIDE + kk + tg + 4];
            }
#pragma unroll
            for (int ni = 0; ni < 8; ni++) {
                int cc = no + ni * 8 + g;
                b[ni][0] = Bb[cc * SMSTRIDE + kk + tg];
                b[ni][1] = Bb[cc * SMSTRIDE + kk + tg + 4];
            }
#pragma unroll
            for (int mi = 0; mi < 2; mi++)
#pragma unroll
                for (int ni = 0; ni < 8; ni++) {
                    asm volatile(
                        "mma.sync.aligned.m16n8k8.row.col.f32.tf32.tf32.f32 "
                        "{%0,%1,%2,%3}, {%4,%5,%6,%7}, {%8,%9}, {%0,%1,%2,%3};"
                        : "+f"(acc[mi][ni][0]), "+f"(acc[mi][ni][1]),
                          "+f"(acc[mi][ni][2]), "+f"(acc[mi][ni][3])
                        : "r"(a[mi][0]), "r"(a[mi][1]),
                          "r"(a[mi][2]), "r"(a[mi][3]),
                          "r"(b[ni][0]), "r"(b[ni][1]));
                }
        }

        // store prefetched tile into the other buffer
        if (kt + 1 < T) {
            const int nxt = (kt + 1) & 1;
#pragma unroll
            for (int s = 0; s < 4; s++) {
                unsigned* da = As + nxt * SMTILE + (r0 + s * 32) * SMSTRIDE + c0;
                da[0] = f2tf(pa[s].x); da[1] = f2tf(pa[s].y);
                da[2] = f2tf(pa[s].z); da[3] = f2tf(pa[s].w);
                unsigned* db = Bs + nxt * SMTILE + (r0 + s * 32) * SMSTRIDE + c0;
                db[0] = f2tf(pb[s].x); db[1] = f2tf(pb[s].y);
                db[2] = f2tf(pb[s].z); db[3] = f2tf(pb[s].w);
            }
        }
        __syncthreads();
    }

    // --- epilogue: bias (+ tanh), float2 stores ---
#pragma unroll
    for (int mi = 0; mi < 2; mi++) {
        size_t row0 = rowBase + mo + mi * 16 + g;
#pragma unroll
        for (int ni = 0; ni < 8; ni++) {
            int col = (int)colBase + no + ni * 8 + 2 * tg;
            float bb0 = __ldg(&bias[col]);
            float bb1 = __ldg(&bias[col + 1]);
            float v0 = acc[mi][ni][0] + bb0;
            float v1 = acc[mi][ni][1] + bb1;
            float v2 = acc[mi][ni][2] + bb0;
            float v3 = acc[mi][ni][3] + bb1;
            if (TANH) {
                v0 = tanhf(v0); v1 = tanhf(v1);
                v2 = tanhf(v2); v3 = tanhf(v3);
            }
            float2 p0 = make_float2(v0, v1);
            float2 p1 = make_float2(v2, v3);
            *(float2*)&C[row0 * N + col]       = p0;
            *(float2*)&C[(row0 + 8) * N + col] = p1;
        }
    }
}

// ---------------------------------------------------------------------------
// Launch
// ---------------------------------------------------------------------------
extern "C" void kernel_launch(void* const* d_in, const int* in_sizes, int n_in,
                              void* d_out, int out_size) {
    const float* x     = (const float*)d_in[0];
    const float* gamma = (const float*)d_in[1];
    const float* beta  = (const float*)d_in[2];
    const float* W1    = (const float*)d_in[3];
    const float* b1    = (const float*)d_in[4];
    const float* W2    = (const float*)d_in[5];
    const float* b2    = (const float*)d_in[6];
    const float* Wf    = (const float*)d_in[7];
    const float* bf    = (const float*)d_in[8];

    float* out = (float*)d_out;                         // [N, 256] tanh(final)
    float* raw = out + (size_t)NROWS * DIM;             // [N, 256] tanh(xn)

    float *xn_p, *h1_p, *h2_p;
    cudaGetSymbolAddress((void**)&xn_p, g_xn);
    cudaGetSymbolAddress((void**)&h1_p, g_h1);
    cudaGetSymbolAddress((void**)&h2_p, g_h2);

    const size_t smem = 4 * SMTILE * sizeof(unsigned);  // 73728 B
    cudaFuncSetAttribute(gemm_tn<false>,
                         cudaFuncAttributeMaxDynamicSharedMemorySize, (int)smem);
    cudaFuncSetAttribute(gemm_tn<true>,
                         cudaFuncAttributeMaxDynamicSharedMemorySize, (int)smem);

    bn_partial<<<256, 256>>>(x);
    bn_final<<<1, 256>>>(gamma, beta);
    bn_norm_tanh<<<(NROWS * DIM / 4) / 256, 256>>>((const float4*)x,
                                                   (float4*)raw, (float4*)xn_p);

    gemm_tn<false><<<dim3(H1 / 128, NROWS / 128), 256, smem>>>(
        xn_p, W1, b1, h1_p, NROWS, H1, DIM);
    gemm_tn<false><<<dim3(H2 / 128, NROWS / 128), 256, smem>>>(
        h1_p, W2, b2, h2_p, NROWS, H2, H1);
    gemm_tn<true><<<dim3(DIM / 128, NROWS / 128), 256, smem>>>(
        h2_p, Wf, bf, out, NROWS, DIM, H2);
}

// round 3
// speedup vs baseline: 1.0557x; 1.0557x over previous
#include <cuda_runtime.h>
#include <math.h>
#include <cstdint>

#define NROWS 65536
#define DIM   256
#define H1    512
#define H2    2048

// ---------------------------------------------------------------------------
// Device scratch (allocation-free rule)
// ---------------------------------------------------------------------------
__device__ __align__(16) float g_partS[256 * 256];
__device__ __align__(16) float g_partQ[256 * 256];
__device__ __align__(16) float g_scale[DIM];
__device__ __align__(16) float g_shift[DIM];
__device__ __align__(16) float g_xn[(size_t)NROWS * DIM];    //  64 MB (tf32-rounded)
__device__ __align__(16) float g_h1[(size_t)NROWS * H1];     // 128 MB (tf32-rounded)
__device__ __align__(16) float g_h2[(size_t)NROWS * H2];     // 512 MB (tf32-rounded)
__device__ __align__(16) float g_w1r[H1 * DIM];
__device__ __align__(16) float g_w2r[H2 * H1];
__device__ __align__(16) float g_wfr[DIM * H2];

__device__ __forceinline__ unsigned f2tf(float f) {
    unsigned u;
    asm("cvt.rna.tf32.f32 %0, %1;" : "=r"(u) : "f"(f));
    return u;
}
__device__ __forceinline__ uint32_t smem_u32(const void* p) {
    uint32_t a;
    asm("{ .reg .u64 t; cvta.to.shared.u64 t, %1; cvt.u32.u64 %0, t; }"
        : "=r"(a) : "l"(p));
    return a;
}
__device__ __forceinline__ void cp16(uint32_t dst, const void* src) {
    asm volatile("cp.async.cg.shared.global [%0], [%1], 16;"
                 :: "r"(dst), "l"(src));
}
__device__ __forceinline__ void cp_commit() {
    asm volatile("cp.async.commit_group;" ::: "memory");
}
template <int N>
__device__ __forceinline__ void cp_wait() {
    asm volatile("cp.async.wait_group %0;" :: "n"(N) : "memory");
}

// ---------------------------------------------------------------------------
// BN kernels
// ---------------------------------------------------------------------------
__global__ void bn_partial(const float* __restrict__ x) {
    int c = threadIdx.x, b = blockIdx.x;
    const float* xp = x + (size_t)b * 256 * DIM + c;
    float s = 0.f, q = 0.f;
#pragma unroll 8
    for (int r = 0; r < 256; r++) {
        float v = xp[(size_t)r * DIM];
        s += v; q += v * v;
    }
    g_partS[b * 256 + c] = s;
    g_partQ[b * 256 + c] = q;
}

__global__ void bn_final(const float* __restrict__ gamma,
                         const float* __restrict__ beta) {
    int c = threadIdx.x;
    float s = 0.f, q = 0.f;
#pragma unroll 4
    for (int b = 0; b < 256; b++) {
        s += g_partS[b * 256 + c];
        q += g_partQ[b * 256 + c];
    }
    const float inv = 1.0f / (float)NROWS;
    float mu  = s * inv;
    float var = q * inv - mu * mu;
    float sc  = gamma[c] * rsqrtf(var + 1e-5f);
    g_scale[c] = sc;
    g_shift[c] = beta[c] - mu * sc;
}

// xn (tf32-RNA) -> scratch; raw = tanh(exact xn) -> out tail
__global__ void bn_norm_tanh(const float4* __restrict__ x4,
                             float4* __restrict__ raw4,
                             float4* __restrict__ xn4) {
    int i = blockIdx.x * blockDim.x + threadIdx.x;
    int c0 = (i * 4) & (DIM - 1);
    float4 v = x4[i];
    float4 xn;
    xn.x = v.x * g_scale[c0 + 0] + g_shift[c0 + 0];
    xn.y = v.y * g_scale[c0 + 1] + g_shift[c0 + 1];
    xn.z = v.z * g_scale[c0 + 2] + g_shift[c0 + 2];
    xn.w = v.w * g_scale[c0 + 3] + g_shift[c0 + 3];
    float4 t;
    t.x = tanhf(xn.x); t.y = tanhf(xn.y);
    t.z = tanhf(xn.z); t.w = tanhf(xn.w);
    raw4[i] = t;
    float4 xr;
    xr.x = __uint_as_float(f2tf(xn.x));
    xr.y = __uint_as_float(f2tf(xn.y));
    xr.z = __uint_as_float(f2tf(xn.z));
    xr.w = __uint_as_float(f2tf(xn.w));
    xn4[i] = xr;
}

__global__ void round_tf32(const float4* __restrict__ src, float4* __restrict__ dst,
                           int n4) {
    int i = blockIdx.x * blockDim.x + threadIdx.x;
    if (i < n4) {
        float4 v = src[i];
        v.x = __uint_as_float(f2tf(v.x));
        v.y = __uint_as_float(f2tf(v.y));
        v.z = __uint_as_float(f2tf(v.z));
        v.w = __uint_as_float(f2tf(v.w));
        dst[i] = v;
    }
}

// ---------------------------------------------------------------------------
// GEMM: C[M,N] = A[M,K] @ W[N,K]^T + bias
//   MODE 0: output rounded to tf32 (intermediate layers)
//   MODE 1: output tanh'd (final layer)
// Block tile 128x256, BK=32, 256 threads = 8 warps of 64x64.
// cp.async.cg 3-stage pipeline; inputs are pre-rounded tf32 bit patterns.
// ---------------------------------------------------------------------------
#define SMSTRIDE   36                         // words: 32 + 4 pad
#define ROWBYTES   (SMSTRIDE * 4)             // 144
#define A_BYTES    (128 * ROWBYTES)           // 18432
#define B_BYTES    (256 * ROWBYTES)           // 36864
#define STAGE_B    (A_BYTES + B_BYTES)        // 55296
#define STAGES     3
#define GEMM_SMEM  (STAGES * STAGE_B)         // 165888

__device__ __forceinline__ void issue_tile(const float* aPtr, const float* bPtr,
                                           uint32_t sA, uint32_t sB,
                                           int kOff, int K) {
#pragma unroll
    for (int j = 0; j < 4; j++)
        cp16(sA + j * 32 * ROWBYTES, aPtr + (size_t)j * 32 * K + kOff);
#pragma unroll
    for (int j = 0; j < 8; j++)
        cp16(sB + j * 32 * ROWBYTES, bPtr + (size_t)j * 32 * K + kOff);
}

template <int MODE>
__global__ __launch_bounds__(256, 1)
void gemm_tn(const float* __restrict__ A, const float* __restrict__ W,
             const float* __restrict__ bias, float* __restrict__ C,
             int N, int K) {
    extern __shared__ char smem[];
    const uint32_t sbase = smem_u32(smem);

    const int tid  = threadIdx.x;
    const int lane = tid & 31;
    const int g    = lane >> 2;
    const int tg   = lane & 3;
    const int wid  = tid >> 5;
    const int wm   = (wid & 1) * 64;     // warp M offset
    const int wn   = (wid >> 1) * 64;    // warp N offset

    const size_t rowBase = (size_t)blockIdx.y * 128;
    const size_t colBase = (size_t)blockIdx.x * 256;
    const int T = K >> 5;

    // per-thread cp.async source/dest bases
    const int r0 = tid >> 3;          // 0..31
    const int c0 = tid & 7;           // 0..7 (16B chunk)
    const float* aPtr = A + (rowBase + r0) * (size_t)K + c0 * 4;
    const float* bPtr = W + (colBase + r0) * (size_t)K + c0 * 4;
    const uint32_t sAo = r0 * ROWBYTES + c0 * 16;
    const uint32_t sBo = A_BYTES + r0 * ROWBYTES + c0 * 16;

    float acc[4][8][4];
#pragma unroll
    for (int mi = 0; mi < 4; mi++)
#pragma unroll
        for (int ni = 0; ni < 8; ni++)
#pragma unroll
            for (int k = 0; k < 4; k++) acc[mi][ni][k] = 0.f;

    // prologue: stages 0,1
    issue_tile(aPtr, bPtr, sbase + sAo, sbase + sBo, 0, K);
    cp_commit();
    issue_tile(aPtr, bPtr, sbase + STAGE_B + sAo, sbase + STAGE_B + sBo, 32, K);
    cp_commit();

    for (int kt = 0; kt < T; kt++) {
        cp_wait<1>();
        __syncthreads();

        // prefetch tile kt+2 into slot (kt+2)%3 (freed by compute of kt-1)
        if (kt + 2 < T) {
            uint32_t sb2 = sbase + ((kt + 2) % STAGES) * STAGE_B;
            issue_tile(aPtr, bPtr, sb2 + sAo, sb2 + sBo, (kt + 2) * 32, K);
        }
        cp_commit();   // unconditional: keeps group count in lockstep

        const unsigned* As = (const unsigned*)(smem + (kt % STAGES) * STAGE_B);
        const unsigned* Bs = (const unsigned*)(smem + (kt % STAGES) * STAGE_B + A_BYTES);

#pragma unroll
        for (int kk = 0; kk < 32; kk += 8) {
            unsigned a[4][4], b[8][2];
#pragma unroll
            for (int mi = 0; mi < 4; mi++) {
                int rr = wm + mi * 16;
                a[mi][0] = As[(rr + g)     * SMSTRIDE + kk + tg];
                a[mi][1] = As[(rr + g + 8) * SMSTRIDE + kk + tg];
                a[mi][2] = As[(rr + g)     * SMSTRIDE + kk + tg + 4];
                a[mi][3] = As[(rr + g + 8) * SMSTRIDE + kk + tg + 4];
            }
#pragma unroll
            for (int ni = 0; ni < 8; ni++) {
                int cc = wn + ni * 8 + g;
                b[ni][0] = Bs[cc * SMSTRIDE + kk + tg];
                b[ni][1] = Bs[cc * SMSTRIDE + kk + tg + 4];
            }
#pragma unroll
            for (int mi = 0; mi < 4; mi++)
#pragma unroll
                for (int ni = 0; ni < 8; ni++) {
                    asm volatile(
                        "mma.sync.aligned.m16n8k8.row.col.f32.tf32.tf32.f32 "
                        "{%0,%1,%2,%3}, {%4,%5,%6,%7}, {%8,%9}, {%0,%1,%2,%3};"
                        : "+f"(acc[mi][ni][0]), "+f"(acc[mi][ni][1]),
                          "+f"(acc[mi][ni][2]), "+f"(acc[mi][ni][3])
                        : "r"(a[mi][0]), "r"(a[mi][1]),
                          "r"(a[mi][2]), "r"(a[mi][3]),
                          "r"(b[ni][0]), "r"(b[ni][1]));
                }
        }
    }

    // epilogue
#pragma unroll
    for (int mi = 0; mi < 4; mi++) {
        size_t row0 = rowBase + wm + mi * 16 + g;
#pragma unroll
        for (int ni = 0; ni < 8; ni++) {
            int col = (int)colBase + wn + ni * 8 + 2 * tg;
            float bb0 = __ldg(&bias[col]);
            float bb1 = __ldg(&bias[col + 1]);
            float v0 = acc[mi][ni][0] + bb0;
            float v1 = acc[mi][ni][1] + bb1;
            float v2 = acc[mi][ni][2] + bb0;
            float v3 = acc[mi][ni][3] + bb1;
            if (MODE == 1) {
                v0 = tanhf(v0); v1 = tanhf(v1);
                v2 = tanhf(v2); v3 = tanhf(v3);
            } else {
                v0 = __uint_as_float(f2tf(v0));
                v1 = __uint_as_float(f2tf(v1));
                v2 = __uint_as_float(f2tf(v2));
                v3 = __uint_as_float(f2tf(v3));
            }
            *(float2*)&C[row0 * N + col]       = make_float2(v0, v1);
            *(float2*)&C[(row0 + 8) * N + col] = make_float2(v2, v3);
        }
    }
}

// ---------------------------------------------------------------------------
// Launch
// ---------------------------------------------------------------------------
extern "C" void kernel_launch(void* const* d_in, const int* in_sizes, int n_in,
                              void* d_out, int out_size) {
    const float* x     = (const float*)d_in[0];
    const float* gamma = (const float*)d_in[1];
    const float* beta  = (const float*)d_in[2];
    const float* W1    = (const float*)d_in[3];
    const float* b1    = (const float*)d_in[4];
    const float* W2    = (const float*)d_in[5];
    const float* b2    = (const float*)d_in[6];
    const float* Wf    = (const float*)d_in[7];
    const float* bf    = (const float*)d_in[8];

    float* out = (float*)d_out;
    float* raw = out + (size_t)NROWS * DIM;

    float *xn_p, *h1_p, *h2_p, *w1r, *w2r, *wfr;
    cudaGetSymbolAddress((void**)&xn_p, g_xn);
    cudaGetSymbolAddress((void**)&h1_p, g_h1);
    cudaGetSymbolAddress((void**)&h2_p, g_h2);
    cudaGetSymbolAddress((void**)&w1r, g_w1r);
    cudaGetSymbolAddress((void**)&w2r, g_w2r);
    cudaGetSymbolAddress((void**)&wfr, g_wfr);

    cudaFuncSetAttribute(gemm_tn<0>,
                         cudaFuncAttributeMaxDynamicSharedMemorySize, GEMM_SMEM);
    cudaFuncSetAttribute(gemm_tn<1>,
                         cudaFuncAttributeMaxDynamicSharedMemorySize, GEMM_SMEM);

    bn_partial<<<256, 256>>>(x);
    bn_final<<<1, 256>>>(gamma, beta);
    bn_norm_tanh<<<(NROWS * DIM / 4) / 256, 256>>>((const float4*)x,
                                                   (float4*)raw, (float4*)xn_p);

    round_tf32<<<(H1 * DIM / 4 + 255) / 256, 256>>>((const float4*)W1,
                                                    (float4*)w1r, H1 * DIM / 4);
    round_tf32<<<(H2 * H1 / 4 + 255) / 256, 256>>>((const float4*)W2,
                                                   (float4*)w2r, H2 * H1 / 4);
    round_tf32<<<(DIM * H2 / 4 + 255) / 256, 256>>>((const float4*)Wf,
                                                    (float4*)wfr, DIM * H2 / 4);

    gemm_tn<0><<<dim3(H1 / 256, NROWS / 128), 256, GEMM_SMEM>>>(
        xn_p, w1r, b1, h1_p, H1, DIM);
    gemm_tn<0><<<dim3(H2 / 256, NROWS / 128), 256, GEMM_SMEM>>>(
        h1_p, w2r, b2, h2_p, H2, H1);
    gemm_tn<1><<<dim3(DIM / 256, NROWS / 128), 256, GEMM_SMEM>>>(
        h2_p, wfr, bf, out, DIM, H2);
}

// round 4
// speedup vs baseline: 7.3246x; 6.9383x over previous
#include <cuda_runtime.h>
#include <math.h>
#include <cstdint>

#define NROWS 65536
#define DIM   256
#define H1    512
#define H2    2048

// ---------------------------------------------------------------------------
// Device scratch (allocation-free rule) — ~12 MB total
// ---------------------------------------------------------------------------
__device__ __align__(16) float g_partS[256 * 256];
__device__ __align__(16) float g_partQ[256 * 256];
__device__ __align__(16) float g_scale[DIM];
__device__ __align__(16) float g_shift[DIM];
__device__ __align__(16) float g_w1t[DIM * H1];      // W1^T, tf32-rounded [256,512]
__device__ __align__(16) float g_w2r[H2 * H1];       // W2 rounded
__device__ __align__(16) float g_wfr[DIM * H2];      // Wf rounded
__device__ __align__(16) float g_t2[H2];             // W2@b1 + b2
__device__ __align__(16) float g_beff[DIM];          // Wf@t2 + bf
__device__ __align__(16) float g_t1t[DIM * H2];      // (W2@W1)^T rounded [256,2048]
__device__ __align__(16) float g_wpart[8 * DIM * DIM];
__device__ __align__(16) float g_weff[DIM * DIM];    // Wf@W2@W1 rounded [256,256]
__device__ __align__(16) float g_zbias[H2];          // zero-init, never written

// ---------------------------------------------------------------------------
// Helpers
// ---------------------------------------------------------------------------
__device__ __forceinline__ unsigned f2tf(float f) {
    unsigned u;
    asm("cvt.rna.tf32.f32 %0, %1;" : "=r"(u) : "f"(f));
    return u;
}
__device__ __forceinline__ uint32_t smem_u32(const void* p) {
    uint32_t a;
    asm("{ .reg .u64 t; cvta.to.shared.u64 t, %1; cvt.u32.u64 %0, t; }"
        : "=r"(a) : "l"(p));
    return a;
}
__device__ __forceinline__ void cp16(uint32_t dst, const void* src) {
    asm volatile("cp.async.cg.shared.global [%0], [%1], 16;"
                 :: "r"(dst), "l"(src));
}
__device__ __forceinline__ void cp_commit() {
    asm volatile("cp.async.commit_group;" ::: "memory");
}
template <int N>
__device__ __forceinline__ void cp_wait() {
    asm volatile("cp.async.wait_group %0;" :: "n"(N) : "memory");
}

// ---------------------------------------------------------------------------
// BN stats
// ---------------------------------------------------------------------------
__global__ void bn_partial(const float* __restrict__ x) {
    int c = threadIdx.x, b = blockIdx.x;
    const float* xp = x + (size_t)b * 256 * DIM + c;
    float s = 0.f, q = 0.f;
#pragma unroll 8
    for (int r = 0; r < 256; r++) {
        float v = xp[(size_t)r * DIM];
        s += v; q += v * v;
    }
    g_partS[b * 256 + c] = s;
    g_partQ[b * 256 + c] = q;
}

__global__ void bn_final(const float* __restrict__ gamma,
                         const float* __restrict__ beta) {
    int c = threadIdx.x;
    float s = 0.f, q = 0.f;
#pragma unroll 4
    for (int b = 0; b < 256; b++) {
        s += g_partS[b * 256 + c];
        q += g_partQ[b * 256 + c];
    }
    const float inv = 1.0f / (float)NROWS;
    float mu  = s * inv;
    float var = q * inv - mu * mu;
    float sc  = gamma[c] * rsqrtf(var + 1e-5f);
    g_scale[c] = sc;
    g_shift[c] = beta[c] - mu * sc;
}

// ---------------------------------------------------------------------------
// prep_weights: one kernel, grid-partitioned.
//  blocks [0,256)    : t2 = W2@b1 + b2 (warp per row, fp32 exact)
//  blocks [256,768)  : W1 transpose + tf32 round -> g_w1t
//  blocks [768,1792) : round W2 -> g_w2r
//  blocks [1792,2304): round Wf -> g_wfr
// ---------------------------------------------------------------------------
__global__ void prep_weights(const float* __restrict__ W1,
                             const float* __restrict__ W2,
                             const float* __restrict__ Wf,
                             const float* __restrict__ b1,
                             const float* __restrict__ b2) {
    int bx = blockIdx.x, tid = threadIdx.x;
    if (bx < 256) {
        int w = tid >> 5, lane = tid & 31;
        int row = bx * 8 + w;
        const float* wr = W2 + (size_t)row * H1;
        float s = 0.f;
#pragma unroll
        for (int i = 0; i < H1 / 32; i++)
            s += wr[lane + i * 32] * b1[lane + i * 32];
#pragma unroll
        for (int o = 16; o; o >>= 1) s += __shfl_xor_sync(~0u, s, o);
        if (lane == 0) g_t2[row] = s + b2[row];
    } else if (bx < 768) {
        int e = (bx - 256) * 256 + tid;          // < 131072
        int k = e >> 8, j = e & 255;
        g_w1t[j * H1 + k] = __uint_as_float(f2tf(W1[e]));
    } else if (bx < 1792) {
        int i = (bx - 768) * 256 + tid;          // float4 idx < 262144
        float4 v = ((const float4*)W2)[i];
        v.x = __uint_as_float(f2tf(v.x));
        v.y = __uint_as_float(f2tf(v.y));
        v.z = __uint_as_float(f2tf(v.z));
        v.w = __uint_as_float(f2tf(v.w));
        ((float4*)g_w2r)[i] = v;
    } else {
        int i = (bx - 1792) * 256 + tid;         // < 131072
        float4 v = ((const float4*)Wf)[i];
        v.x = __uint_as_float(f2tf(v.x));
        v.y = __uint_as_float(f2tf(v.y));
        v.z = __uint_as_float(f2tf(v.z));
        v.w = __uint_as_float(f2tf(v.w));
        ((float4*)g_wfr)[i] = v;
    }
}

// beff = Wf @ t2 + bf (warp per row, fp32 exact). 32 blocks x 256.
__global__ void bias_beff(const float* __restrict__ Wf,
                          const float* __restrict__ bf) {
    int w = threadIdx.x >> 5, lane = threadIdx.x & 31;
    int row = blockIdx.x * 8 + w;
    const float* wr = Wf + (size_t)row * H2;
    float s = 0.f;
#pragma unroll
    for (int i = 0; i < H2 / 32; i++)
        s += wr[lane + i * 32] * g_t2[lane + i * 32];
#pragma unroll
    for (int o = 16; o; o >>= 1) s += __shfl_xor_sync(~0u, s, o);
    if (lane == 0) g_beff[row] = s + bf[row];
}

// weff = sum of 8 split-K partials, rounded. 64 blocks x 256 (float4 each).
__global__ void weff_reduce() {
    int i = blockIdx.x * 256 + threadIdx.x;      // < 16384 float4
    float4 s = ((const float4*)g_wpart)[i];
#pragma unroll
    for (int z = 1; z < 8; z++) {
        float4 p = ((const float4*)g_wpart)[z * 16384 + i];
        s.x += p.x; s.y += p.y; s.z += p.z; s.w += p.w;
    }
    s.x = __uint_as_float(f2tf(s.x));
    s.y = __uint_as_float(f2tf(s.y));
    s.z = __uint_as_float(f2tf(s.z));
    s.w = __uint_as_float(f2tf(s.w));
    ((float4*)g_weff)[i] = s;
}

// ---------------------------------------------------------------------------
// tf32 GEMM: C = A[M,K] @ W[N,K]^T (+bias).  MODE 0: round+bias.
// MODE 2: split-K partial (offset by blockIdx.z, raw fp32, no bias).
// Block 128x256, BK=32, 256 thr = 8 warps of 64x64. 3-stage cp.async.
// ---------------------------------------------------------------------------
#define SMSTRIDE   36
#define ROWBYTES   (SMSTRIDE * 4)
#define A_BYTES    (128 * ROWBYTES)
#define B_BYTES    (256 * ROWBYTES)
#define STAGE_B    (A_BYTES + B_BYTES)
#define STAGES     3
#define GEMM_SMEM  (STAGES * STAGE_B)

__device__ __forceinline__ void issue_tile(const float* aPtr, const float* bPtr,
                                           uint32_t sA, uint32_t sB,
                                           int kOff, int K) {
#pragma unroll
    for (int j = 0; j < 4; j++)
        cp16(sA + j * 32 * ROWBYTES, aPtr + (size_t)j * 32 * K + kOff);
#pragma unroll
    for (int j = 0; j < 8; j++)
        cp16(sB + j * 32 * ROWBYTES, bPtr + (size_t)j * 32 * K + kOff);
}

template <int MODE>
__global__ __launch_bounds__(256, 1)
void gemm_tn(const float* __restrict__ A, const float* __restrict__ W,
             const float* __restrict__ bias, float* __restrict__ C,
             int N, int K, int kloop) {
    extern __shared__ char smem[];
    const uint32_t sbase = smem_u32(smem);

    const int tid  = threadIdx.x;
    const int lane = tid & 31;
    const int g    = lane >> 2;
    const int tg   = lane & 3;
    const int wid  = tid >> 5;
    const int wm   = (wid & 1) * 64;
    const int wn   = (wid >> 1) * 64;

    if (MODE == 2) {
        A += (size_t)blockIdx.z * kloop;
        W += (size_t)blockIdx.z * kloop;
        C += (size_t)blockIdx.z * (size_t)gridDim.y * 128 * N;
    }

    const size_t rowBase = (size_t)blockIdx.y * 128;
    const size_t colBase = (size_t)blockIdx.x * 256;
    const int T = kloop >> 5;

    const int r0 = tid >> 3;
    const int c0 = tid & 7;
    const float* aPtr = A + (rowBase + r0) * (size_t)K + c0 * 4;
    const float* bPtr = W + (colBase + r0) * (size_t)K + c0 * 4;
    const uint32_t sAo = r0 * ROWBYTES + c0 * 16;
    const uint32_t sBo = A_BYTES + r0 * ROWBYTES + c0 * 16;

    float acc[4][8][4];
#pragma unroll
    for (int mi = 0; mi < 4; mi++)
#pragma unroll
        for (int ni = 0; ni < 8; ni++)
#pragma unroll
            for (int k = 0; k < 4; k++) acc[mi][ni][k] = 0.f;

    issue_tile(aPtr, bPtr, sbase + sAo, sbase + sBo, 0, K);
    cp_commit();
    issue_tile(aPtr, bPtr, sbase + STAGE_B + sAo, sbase + STAGE_B + sBo, 32, K);
    cp_commit();

    for (int kt = 0; kt < T; kt++) {
        cp_wait<1>();
        __syncthreads();

        if (kt + 2 < T) {
            uint32_t sb2 = sbase + ((kt + 2) % STAGES) * STAGE_B;
            issue_tile(aPtr, bPtr, sb2 + sAo, sb2 + sBo, (kt + 2) * 32, K);
        }
        cp_commit();

        const unsigned* As = (const unsigned*)(smem + (kt % STAGES) * STAGE_B);
        const unsigned* Bs = (const unsigned*)(smem + (kt % STAGES) * STAGE_B + A_BYTES);

#pragma unroll
        for (int kk = 0; kk < 32; kk += 8) {
            unsigned a[4][4], b[8][2];
#pragma unroll
            for (int mi = 0; mi < 4; mi++) {
                int rr = wm + mi * 16;
                a[mi][0] = As[(rr + g)     * SMSTRIDE + kk + tg];
                a[mi][1] = As[(rr + g + 8) * SMSTRIDE + kk + tg];
                a[mi][2] = As[(rr + g)     * SMSTRIDE + kk + tg + 4];
                a[mi][3] = As[(rr + g + 8) * SMSTRIDE + kk + tg + 4];
            }
#pragma unroll
            for (int ni = 0; ni < 8; ni++) {
                int cc = wn + ni * 8 + g;
                b[ni][0] = Bs[cc * SMSTRIDE + kk + tg];
                b[ni][1] = Bs[cc * SMSTRIDE + kk + tg + 4];
            }
#pragma unroll
            for (int mi = 0; mi < 4; mi++)
#pragma unroll
                for (int ni = 0; ni < 8; ni++) {
                    asm volatile(
                        "mma.sync.aligned.m16n8k8.row.col.f32.tf32.tf32.f32 "
                        "{%0,%1,%2,%3}, {%4,%5,%6,%7}, {%8,%9}, {%0,%1,%2,%3};"
                        : "+f"(acc[mi][ni][0]), "+f"(acc[mi][ni][1]),
                          "+f"(acc[mi][ni][2]), "+f"(acc[mi][ni][3])
                        : "r"(a[mi][0]), "r"(a[mi][1]),
                          "r"(a[mi][2]), "r"(a[mi][3]),
                          "r"(b[ni][0]), "r"(b[ni][1]));
                }
        }
    }

#pragma unroll
    for (int mi = 0; mi < 4; mi++) {
        size_t row0 = rowBase + wm + mi * 16 + g;
#pragma unroll
        for (int ni = 0; ni < 8; ni++) {
            int col = (int)colBase + wn + ni * 8 + 2 * tg;
            float v0 = acc[mi][ni][0], v1 = acc[mi][ni][1];
            float v2 = acc[mi][ni][2], v3 = acc[mi][ni][3];
            if (MODE == 0) {
                float bb0 = __ldg(&bias[col]);
                float bb1 = __ldg(&bias[col + 1]);
                v0 = __uint_as_float(f2tf(v0 + bb0));
                v1 = __uint_as_float(f2tf(v1 + bb1));
                v2 = __uint_as_float(f2tf(v2 + bb0));
                v3 = __uint_as_float(f2tf(v3 + bb1));
            }
            *(float2*)&C[row0 * N + col]       = make_float2(v0, v1);
            *(float2*)&C[(row0 + 8) * N + col] = make_float2(v2, v3);
        }
    }
}

// ---------------------------------------------------------------------------
// Fused final: per 128-row tile —
//   xn = x*scale+shift; raw = tanh(xn); A = tf32(xn) fully resident in smem;
//   stream Weff (tf32) k-tiles; out = tanh(xn @ Weff^T + beff).
// ---------------------------------------------------------------------------
#define FA_STAGE 18432
#define FB_STAGE 36864
#define FA_TOTAL (8 * FA_STAGE)                 // 147456
#define F_SMEM   (FA_TOTAL + 2 * FB_STAGE)      // 221184

__device__ __forceinline__ void issueB_f(uint32_t sbase, int slot, int kt, int tid) {
#pragma unroll
    for (int j = 0; j < 8; j++) {
        int r = (tid >> 3) + j * 32;
        cp16(sbase + FA_TOTAL + slot * FB_STAGE + r * ROWBYTES + (tid & 7) * 16,
             g_weff + r * 256 + kt * 32 + (tid & 7) * 4);
    }
}

__global__ __launch_bounds__(256, 1)
void fused_final(const float* __restrict__ x, float* __restrict__ raw,
                 float* __restrict__ out) {
    extern __shared__ char smem[];
    const uint32_t sbase = smem_u32(smem);
    const int tid  = threadIdx.x;
    const int lane = tid & 31;
    const int g    = lane >> 2;
    const int tg   = lane & 3;
    const int wid  = tid >> 5;
    const int wm   = (wid & 1) * 64;
    const int wn   = (wid >> 1) * 64;
    const size_t rowBase = (size_t)blockIdx.x * 128;

    // B prologue (overlaps with A phase below)
    issueB_f(sbase, 0, 0, tid);
    cp_commit();
    issueB_f(sbase, 1, 1, tid);
    cp_commit();

    // A phase: normalize + tanh->raw + tf32->smem
#pragma unroll 4
    for (int j = 0; j < 32; j++) {
        int item = tid + j * 256;
        int r = item >> 6, c = item & 63;
        float4 v = *(const float4*)(x + (rowBase + r) * 256 + c * 4);
        float4 sc = ((const float4*)g_scale)[c];
        float4 sh = ((const float4*)g_shift)[c];
        float4 xn;
        xn.x = fmaf(v.x, sc.x, sh.x);
        xn.y = fmaf(v.y, sc.y, sh.y);
        xn.z = fmaf(v.z, sc.z, sh.z);
        xn.w = fmaf(v.w, sc.w, sh.w);
        float4 t;
        t.x = tanhf(xn.x); t.y = tanhf(xn.y);
        t.z = tanhf(xn.z); t.w = tanhf(xn.w);
        *(float4*)(raw + (rowBase + r) * 256 + c * 4) = t;
        uint4 rb;
        rb.x = f2tf(xn.x); rb.y = f2tf(xn.y);
        rb.z = f2tf(xn.z); rb.w = f2tf(xn.w);
        *(uint4*)(smem + (c >> 3) * FA_STAGE + r * ROWBYTES + (c & 7) * 16) = rb;
    }

    float acc[4][8][4];
#pragma unroll
    for (int mi = 0; mi < 4; mi++)
#pragma unroll
        for (int ni = 0; ni < 8; ni++)
#pragma unroll
            for (int k = 0; k < 4; k++) acc[mi][ni][k] = 0.f;

    for (int kt = 0; kt < 8; kt++) {
        cp_wait<1>();
        __syncthreads();
        const unsigned* As = (const unsigned*)(smem + kt * FA_STAGE);
        const unsigned* Bs = (const unsigned*)(smem + FA_TOTAL + (kt & 1) * FB_STAGE);

#pragma unroll
        for (int kk = 0; kk < 32; kk += 8) {
            unsigned a[4][4], b[8][2];
#pragma unroll
            for (int mi = 0; mi < 4; mi++) {
                int rr = wm + mi * 16;
                a[mi][0] = As[(rr + g)     * SMSTRIDE + kk + tg];
                a[mi][1] = As[(rr + g + 8) * SMSTRIDE + kk + tg];
                a[mi][2] = As[(rr + g)     * SMSTRIDE + kk + tg + 4];
                a[mi][3] = As[(rr + g + 8) * SMSTRIDE + kk + tg + 4];
            }
#pragma unroll
            for (int ni = 0; ni < 8; ni++) {
                int cc = wn + ni * 8 + g;
                b[ni][0] = Bs[cc * SMSTRIDE + kk + tg];
                b[ni][1] = Bs[cc * SMSTRIDE + kk + tg + 4];
            }
#pragma unroll
            for (int mi = 0; mi < 4; mi++)
#pragma unroll
                for (int ni = 0; ni < 8; ni++) {
                    asm volatile(
                        "mma.sync.aligned.m16n8k8.row.col.f32.tf32.tf32.f32 "
                        "{%0,%1,%2,%3}, {%4,%5,%6,%7}, {%8,%9}, {%0,%1,%2,%3};"
                        : "+f"(acc[mi][ni][0]), "+f"(acc[mi][ni][1]),
                          "+f"(acc[mi][ni][2]), "+f"(acc[mi][ni][3])
                        : "r"(a[mi][0]), "r"(a[mi][1]),
                          "r"(a[mi][2]), "r"(a[mi][3]),
                          "r"(b[ni][0]), "r"(b[ni][1]));
                }
        }
        __syncthreads();          // all warps done reading B slot kt&1
        if (kt + 2 < 8) issueB_f(sbase, kt & 1, kt + 2, tid);
        cp_commit();
    }

    // epilogue: + beff, tanh, store
#pragma unroll
    for (int mi = 0; mi < 4; mi++) {
        size_t row0 = rowBase + wm + mi * 16 + g;
#pragma unroll
        for (int ni = 0; ni < 8; ni++) {
            int col = wn + ni * 8 + 2 * tg;
            float v0 = tanhf(acc[mi][ni][0] + g_beff[col]);
            float v1 = tanhf(acc[mi][ni][1] + g_beff[col + 1]);
            float v2 = tanhf(acc[mi][ni][2] + g_beff[col]);
            float v3 = tanhf(acc[mi][ni][3] + g_beff[col + 1]);
            *(float2*)&out[row0 * 256 + col]       = make_float2(v0, v1);
            *(float2*)&out[(row0 + 8) * 256 + col] = make_float2(v2, v3);
        }
    }
}

// ---------------------------------------------------------------------------
// Launch
// ---------------------------------------------------------------------------
extern "C" void kernel_launch(void* const* d_in, const int* in_sizes, int n_in,
                              void* d_out, int out_size) {
    const float* x     = (const float*)d_in[0];
    const float* gamma = (const float*)d_in[1];
    const float* beta  = (const float*)d_in[2];
    const float* W1    = (const float*)d_in[3];
    const float* b1    = (const float*)d_in[4];
    const float* W2    = (const float*)d_in[5];
    const float* b2    = (const float*)d_in[6];
    const float* Wf    = (const float*)d_in[7];
    const float* bf    = (const float*)d_in[8];

    float* out = (float*)d_out;
    float* raw = out + (size_t)NROWS * DIM;

    float *w1t, *w2r, *wfr, *t1t, *wpart, *zb;
    cudaGetSymbolAddress((void**)&w1t,   g_w1t);
    cudaGetSymbolAddress((void**)&w2r,   g_w2r);
    cudaGetSymbolAddress((void**)&wfr,   g_wfr);
    cudaGetSymbolAddress((void**)&t1t,   g_t1t);
    cudaGetSymbolAddress((void**)&wpart, g_wpart);
    cudaGetSymbolAddress((void**)&zb,    g_zbias);

    cudaFuncSetAttribute(gemm_tn<0>,
                         cudaFuncAttributeMaxDynamicSharedMemorySize, GEMM_SMEM);
    cudaFuncSetAttribute(gemm_tn<2>,
                         cudaFuncAttributeMaxDynamicSharedMemorySize, GEMM_SMEM);
    cudaFuncSetAttribute(fused_final,
                         cudaFuncAttributeMaxDynamicSharedMemorySize, F_SMEM);

    // 1: weight prep (+ t2)
    prep_weights<<<2304, 256>>>(W1, W2, Wf, b1, b2);
    // 2: beff
    bias_beff<<<32, 256>>>(Wf, bf);
    // 3: T1t = (W2@W1)^T  [256,2048]   M=256, N=2048, K=512
    gemm_tn<0><<<dim3(8, 2), 256, GEMM_SMEM>>>(w1t, w2r, zb, t1t,
                                               2048, 512, 512);
    // 4: Weff split-K partials  [8][256,256]   M=256, N=256, K=2048, 8 splits
    gemm_tn<2><<<dim3(1, 2, 8), 256, GEMM_SMEM>>>(wfr, t1t, zb, wpart,
                                                  256, 2048, 256);
    // 5: reduce partials -> Weff (tf32)
    weff_reduce<<<64, 256>>>();
    // 6: BN stats (ncu capture lands here)
    bn_partial<<<256, 256>>>(x);
    // 7
    bn_final<<<1, 256>>>(gamma, beta);
    // 8: fused normalize + raw + GEMM + tanh
    fused_final<<<NROWS / 128, 256, F_SMEM>>>(x, raw, out);
}

// round 5
// speedup vs baseline: 8.6972x; 1.1874x over previous
#include <cuda_runtime.h>
#include <math.h>
#include <cstdint>

#define NROWS 65536
#define DIM   256
#define H1    512
#define H2    2048

// ---------------------------------------------------------------------------
// Device scratch (allocation-free rule) — ~15 MB
// ---------------------------------------------------------------------------
__device__ __align__(16) float g_partS[256 * 256];
__device__ __align__(16) float g_partQ[256 * 256];
__device__ __align__(16) float g_scale[DIM];
__device__ __align__(16) float g_shift[DIM];
__device__ __align__(16) float g_w2t[H1 * H2];        // W2^T rounded [512,2048]
__device__ __align__(16) float g_wfr[DIM * H2];       // Wf rounded   [256,2048]
__device__ __align__(16) float g_t2[H2];              // W2@b1 + b2
__device__ __align__(16) float g_beff[DIM];           // Wf@t2 + bf
__device__ __align__(16) float g_wpart[16 * DIM * H1];// T1 split-K partials (8MB)
__device__ __align__(16) float g_t1[DIM * H1];        // T1 = Wf@W2, fp32 [256,512]
__device__ __align__(16) float g_weff[DIM * DIM];     // Wf@W2@W1 rounded [256,256]

// ---------------------------------------------------------------------------
// Helpers
// ---------------------------------------------------------------------------
__device__ __forceinline__ unsigned f2tf(float f) {
    unsigned u;
    asm("cvt.rna.tf32.f32 %0, %1;" : "=r"(u) : "f"(f));
    return u;
}
__device__ __forceinline__ uint32_t smem_u32(const void* p) {
    uint32_t a;
    asm("{ .reg .u64 t; cvta.to.shared.u64 t, %1; cvt.u32.u64 %0, t; }"
        : "=r"(a) : "l"(p));
    return a;
}
__device__ __forceinline__ void cp16(uint32_t dst, const void* src) {
    asm volatile("cp.async.cg.shared.global [%0], [%1], 16;"
                 :: "r"(dst), "l"(src));
}
__device__ __forceinline__ void cp_commit() {
    asm volatile("cp.async.commit_group;" ::: "memory");
}
template <int N>
__device__ __forceinline__ void cp_wait() {
    asm volatile("cp.async.wait_group %0;" :: "n"(N) : "memory");
}

// ---------------------------------------------------------------------------
// K0 prep: one kernel, 800 blocks.
//   [0,256)    bn partial sums over x
//   [256,512)  W2 transpose + tf32 round -> g_w2t (64x64 tiles)
//   [512,544)  round Wf -> g_wfr
//   [544,800)  t2 = W2@b1 + b2 (warp per row)
// ---------------------------------------------------------------------------
__global__ __launch_bounds__(256)
void prep(const float* __restrict__ x, const float* __restrict__ W2,
          const float* __restrict__ Wf, const float* __restrict__ b1,
          const float* __restrict__ b2) {
    __shared__ float ts[64][65];
    int bx = blockIdx.x, tid = threadIdx.x;
    if (bx < 256) {
        const float* xp = x + (size_t)bx * 256 * DIM + tid;
        float s = 0.f, q = 0.f;
#pragma unroll 8
        for (int r = 0; r < 256; r++) {
            float v = xp[(size_t)r * DIM];
            s += v; q += v * v;
        }
        g_partS[bx * 256 + tid] = s;
        g_partQ[bx * 256 + tid] = q;
    } else if (bx < 512) {
        int b2i = bx - 256;
        int i0 = (b2i & 31) * 64;          // over 2048
        int j0 = (b2i >> 5) * 64;          // over 512
#pragma unroll
        for (int t = 0; t < 16; t++) {
            int e = tid + t * 256;
            int r = e >> 6, c = e & 63;
            ts[r][c] = W2[(size_t)(i0 + r) * H1 + j0 + c];
        }
        __syncthreads();
#pragma unroll
        for (int t = 0; t < 16; t++) {
            int e = tid + t * 256;
            int r = e >> 6, c = e & 63;
            g_w2t[(size_t)(j0 + r) * H2 + i0 + c] =
                __uint_as_float(f2tf(ts[c][r]));
        }
    } else if (bx < 544) {
        int base = (bx - 512) * 4096;      // f4 index
#pragma unroll
        for (int t = 0; t < 16; t++) {
            int i = base + tid + t * 256;
            float4 v = ((const float4*)Wf)[i];
            v.x = __uint_as_float(f2tf(v.x));
            v.y = __uint_as_float(f2tf(v.y));
            v.z = __uint_as_float(f2tf(v.z));
            v.w = __uint_as_float(f2tf(v.w));
            ((float4*)g_wfr)[i] = v;
        }
    } else {
        int w = tid >> 5, lane = tid & 31;
        int row = (bx - 544) * 8 + w;      // < 2048
        const float* wr = W2 + (size_t)row * H1;
        float s = 0.f;
#pragma unroll
        for (int i = 0; i < H1 / 32; i++)
            s += wr[lane + i * 32] * b1[lane + i * 32];
#pragma unroll
        for (int o = 16; o; o >>= 1) s += __shfl_xor_sync(~0u, s, o);
        if (lane == 0) g_t2[row] = s + b2[row];
    }
}

// ---------------------------------------------------------------------------
// K1: T1 split-K partials via tf32 tensor GEMM.
// C = A[M,K]@W[N,K]^T, block 128x256, BK=32, split-K by blockIdx.z.
// ---------------------------------------------------------------------------
#define SMSTRIDE   36
#define ROWBYTES   (SMSTRIDE * 4)
#define A_BYTES    (128 * ROWBYTES)
#define B_BYTES    (256 * ROWBYTES)
#define STAGE_B    (A_BYTES + B_BYTES)
#define STAGES     3
#define GEMM_SMEM  (STAGES * STAGE_B)

__device__ __forceinline__ void issue_tile(const float* aPtr, const float* bPtr,
                                           uint32_t sA, uint32_t sB,
                                           int kOff, int K) {
#pragma unroll
    for (int j = 0; j < 4; j++)
        cp16(sA + j * 32 * ROWBYTES, aPtr + (size_t)j * 32 * K + kOff);
#pragma unroll
    for (int j = 0; j < 8; j++)
        cp16(sB + j * 32 * ROWBYTES, bPtr + (size_t)j * 32 * K + kOff);
}

__global__ __launch_bounds__(256, 1)
void gemm_splitk(const float* __restrict__ A, const float* __restrict__ W,
                 float* __restrict__ C, int N, int K, int kloop) {
    extern __shared__ char smem[];
    const uint32_t sbase = smem_u32(smem);

    const int tid  = threadIdx.x;
    const int lane = tid & 31;
    const int g    = lane >> 2;
    const int tg   = lane & 3;
    const int wid  = tid >> 5;
    const int wm   = (wid & 1) * 64;
    const int wn   = (wid >> 1) * 64;

    A += (size_t)blockIdx.z * kloop;
    W += (size_t)blockIdx.z * kloop;
    C += (size_t)blockIdx.z * (size_t)gridDim.y * 128 * N;

    const size_t rowBase = (size_t)blockIdx.y * 128;
    const size_t colBase = (size_t)blockIdx.x * 256;
    const int T = kloop >> 5;

    const int r0 = tid >> 3;
    const int c0 = tid & 7;
    const float* aPtr = A + (rowBase + r0) * (size_t)K + c0 * 4;
    const float* bPtr = W + (colBase + r0) * (size_t)K + c0 * 4;
    const uint32_t sAo = r0 * ROWBYTES + c0 * 16;
    const uint32_t sBo = A_BYTES + r0 * ROWBYTES + c0 * 16;

    float acc[4][8][4];
#pragma unroll
    for (int mi = 0; mi < 4; mi++)
#pragma unroll
        for (int ni = 0; ni < 8; ni++)
#pragma unroll
            for (int k = 0; k < 4; k++) acc[mi][ni][k] = 0.f;

    issue_tile(aPtr, bPtr, sbase + sAo, sbase + sBo, 0, K);
    cp_commit();
    issue_tile(aPtr, bPtr, sbase + STAGE_B + sAo, sbase + STAGE_B + sBo, 32, K);
    cp_commit();

    for (int kt = 0; kt < T; kt++) {
        cp_wait<1>();
        __syncthreads();

        if (kt + 2 < T) {
            uint32_t sb2 = sbase + ((kt + 2) % STAGES) * STAGE_B;
            issue_tile(aPtr, bPtr, sb2 + sAo, sb2 + sBo, (kt + 2) * 32, K);
        }
        cp_commit();

        const unsigned* As = (const unsigned*)(smem + (kt % STAGES) * STAGE_B);
        const unsigned* Bs = (const unsigned*)(smem + (kt % STAGES) * STAGE_B + A_BYTES);

#pragma unroll
        for (int kk = 0; kk < 32; kk += 8) {
            unsigned a[4][4], b[8][2];
#pragma unroll
            for (int mi = 0; mi < 4; mi++) {
                int rr = wm + mi * 16;
                a[mi][0] = As[(rr + g)     * SMSTRIDE + kk + tg];
                a[mi][1] = As[(rr + g + 8) * SMSTRIDE + kk + tg];
                a[mi][2] = As[(rr + g)     * SMSTRIDE + kk + tg + 4];
                a[mi][3] = As[(rr + g + 8) * SMSTRIDE + kk + tg + 4];
            }
#pragma unroll
            for (int ni = 0; ni < 8; ni++) {
                int cc = wn + ni * 8 + g;
                b[ni][0] = Bs[cc * SMSTRIDE + kk + tg];
                b[ni][1] = Bs[cc * SMSTRIDE + kk + tg + 4];
            }
#pragma unroll
            for (int mi = 0; mi < 4; mi++)
#pragma unroll
                for (int ni = 0; ni < 8; ni++) {
                    asm volatile(
                        "mma.sync.aligned.m16n8k8.row.col.f32.tf32.tf32.f32 "
                        "{%0,%1,%2,%3}, {%4,%5,%6,%7}, {%8,%9}, {%0,%1,%2,%3};"
                        : "+f"(acc[mi][ni][0]), "+f"(acc[mi][ni][1]),
                          "+f"(acc[mi][ni][2]), "+f"(acc[mi][ni][3])
                        : "r"(a[mi][0]), "r"(a[mi][1]),
                          "r"(a[mi][2]), "r"(a[mi][3]),
                          "r"(b[ni][0]), "r"(b[ni][1]));
                }
        }
    }

#pragma unroll
    for (int mi = 0; mi < 4; mi++) {
        size_t row0 = rowBase + wm + mi * 16 + g;
#pragma unroll
        for (int ni = 0; ni < 8; ni++) {
            int col = (int)colBase + wn + ni * 8 + 2 * tg;
            *(float2*)&C[row0 * N + col] =
                make_float2(acc[mi][ni][0], acc[mi][ni][1]);
            *(float2*)&C[(row0 + 8) * N + col] =
                make_float2(acc[mi][ni][2], acc[mi][ni][3]);
        }
    }
}

// ---------------------------------------------------------------------------
// K2: reduce 16 T1 partials -> g_t1 (fp32). 32 blocks x 256, 4 float4 each.
// ---------------------------------------------------------------------------
__global__ void t1_reduce() {
    int base = blockIdx.x * 1024 + threadIdx.x;
#pragma unroll
    for (int t = 0; t < 4; t++) {
        int i = base + t * 256;               // < 32768 f4
        float4 s = ((const float4*)g_wpart)[i];
#pragma unroll
        for (int z = 1; z < 16; z++) {
            float4 p = ((const float4*)g_wpart)[z * 32768 + i];
            s.x += p.x; s.y += p.y; s.z += p.z; s.w += p.w;
        }
        ((float4*)g_t1)[i] = s;
    }
}

// ---------------------------------------------------------------------------
// K3: beff = Wf@t2 + bf (warp per row). 32 blocks.
// ---------------------------------------------------------------------------
__global__ void bias_beff(const float* __restrict__ Wf,
                          const float* __restrict__ bf) {
    int w = threadIdx.x >> 5, lane = threadIdx.x & 31;
    int row = blockIdx.x * 8 + w;
    const float* wr = Wf + (size_t)row * H2;
    float s = 0.f;
#pragma unroll
    for (int i = 0; i < H2 / 32; i++)
        s += wr[lane + i * 32] * g_t2[lane + i * 32];
#pragma unroll
    for (int o = 16; o; o >>= 1) s += __shfl_xor_sync(~0u, s, o);
    if (lane == 0) g_beff[row] = s + bf[row];
}

// ---------------------------------------------------------------------------
// K4: Weff = T1 @ W1 (fp32 FFMA, 32x32 tiles, 64 blocks) + round;
//     block 64 = bn_final.
// ---------------------------------------------------------------------------
__global__ __launch_bounds__(256)
void weff_bnfinal(const float* __restrict__ W1, const float* __restrict__ gamma,
                  const float* __restrict__ beta) {
    int tid = threadIdx.x;
    if (blockIdx.x == 64) {
        float s = 0.f, q = 0.f;
#pragma unroll 4
        for (int b = 0; b < 256; b++) {
            s += g_partS[b * 256 + tid];
            q += g_partQ[b * 256 + tid];
        }
        const float inv = 1.0f / (float)NROWS;
        float mu  = s * inv;
        float var = q * inv - mu * mu;
        float sc  = gamma[tid] * rsqrtf(var + 1e-5f);
        g_scale[tid] = sc;
        g_shift[tid] = beta[tid] - mu * sc;
        return;
    }
    __shared__ float As[32][33], Bs[32][33];
    int i0 = (blockIdx.x >> 3) * 32, j0 = (blockIdx.x & 7) * 32;
    int ty = tid >> 4, tx = tid & 15;
    float a00 = 0.f, a01 = 0.f, a10 = 0.f, a11 = 0.f;
    for (int kb = 0; kb < H1; kb += 32) {
#pragma unroll
        for (int t = 0; t < 4; t++) {
            int e = tid + t * 256;
            int r = e >> 5, c = e & 31;
            As[r][c] = g_t1[(i0 + r) * H1 + kb + c];
            Bs[r][c] = W1[(size_t)(kb + r) * DIM + j0 + c];
        }
        __syncthreads();
#pragma unroll
        for (int k = 0; k < 32; k++) {
            float x0 = As[ty * 2][k],     x1 = As[ty * 2 + 1][k];
            float y0 = Bs[k][tx * 2],     y1 = Bs[k][tx * 2 + 1];
            a00 = fmaf(x0, y0, a00); a01 = fmaf(x0, y1, a01);
            a10 = fmaf(x1, y0, a10); a11 = fmaf(x1, y1, a11);
        }
        __syncthreads();
    }
    int r0 = i0 + ty * 2, c0 = j0 + tx * 2;
    g_weff[r0 * DIM + c0]           = __uint_as_float(f2tf(a00));
    g_weff[r0 * DIM + c0 + 1]       = __uint_as_float(f2tf(a01));
    g_weff[(r0 + 1) * DIM + c0]     = __uint_as_float(f2tf(a10));
    g_weff[(r0 + 1) * DIM + c0 + 1] = __uint_as_float(f2tf(a11));
}

// ---------------------------------------------------------------------------
// K5 fused final: per 128-row tile —
//   xn = x*scale+shift; raw = tanh(xn); A = tf32(xn) resident in smem;
//   stream Weff k-tiles; out = tanh(xn @ Weff^T + beff).
// ---------------------------------------------------------------------------
#define FA_STAGE 18432
#define FB_STAGE 36864
#define FA_TOTAL (8 * FA_STAGE)
#define F_SMEM   (FA_TOTAL + 2 * FB_STAGE)

__device__ __forceinline__ void issueB_f(uint32_t sbase, int slot, int kt, int tid) {
#pragma unroll
    for (int j = 0; j < 8; j++) {
        int r = (tid >> 3) + j * 32;
        cp16(sbase + FA_TOTAL + slot * FB_STAGE + r * ROWBYTES + (tid & 7) * 16,
             g_weff + r * 256 + kt * 32 + (tid & 7) * 4);
    }
}

__global__ __launch_bounds__(256, 1)
void fused_final(const float* __restrict__ x, float* __restrict__ raw,
                 float* __restrict__ out) {
    extern __shared__ char smem[];
    const uint32_t sbase = smem_u32(smem);
    const int tid  = threadIdx.x;
    const int lane = tid & 31;
    const int g    = lane >> 2;
    const int tg   = lane & 3;
    const int wid  = tid >> 5;
    const int wm   = (wid & 1) * 64;
    const int wn   = (wid >> 1) * 64;
    const size_t rowBase = (size_t)blockIdx.x * 128;

    issueB_f(sbase, 0, 0, tid);
    cp_commit();
    issueB_f(sbase, 1, 1, tid);
    cp_commit();

#pragma unroll 4
    for (int j = 0; j < 32; j++) {
        int item = tid + j * 256;
        int r = item >> 6, c = item & 63;
        float4 v = *(const float4*)(x + (rowBase + r) * 256 + c * 4);
        float4 sc = ((const float4*)g_scale)[c];
        float4 sh = ((const float4*)g_shift)[c];
        float4 xn;
        xn.x = fmaf(v.x, sc.x, sh.x);
        xn.y = fmaf(v.y, sc.y, sh.y);
        xn.z = fmaf(v.z, sc.z, sh.z);
        xn.w = fmaf(v.w, sc.w, sh.w);
        float4 t;
        t.x = tanhf(xn.x); t.y = tanhf(xn.y);
        t.z = tanhf(xn.z); t.w = tanhf(xn.w);
        *(float4*)(raw + (rowBase + r) * 256 + c * 4) = t;
        uint4 rb;
        rb.x = f2tf(xn.x); rb.y = f2tf(xn.y);
        rb.z = f2tf(xn.z); rb.w = f2tf(xn.w);
        *(uint4*)(smem + (c >> 3) * FA_STAGE + r * ROWBYTES + (c & 7) * 16) = rb;
    }

    float acc[4][8][4];
#pragma unroll
    for (int mi = 0; mi < 4; mi++)
#pragma unroll
        for (int ni = 0; ni < 8; ni++)
#pragma unroll
            for (int k = 0; k < 4; k++) acc[mi][ni][k] = 0.f;

    for (int kt = 0; kt < 8; kt++) {
        cp_wait<1>();
        __syncthreads();
        const unsigned* As = (const unsigned*)(smem + kt * FA_STAGE);
        const unsigned* Bs = (const unsigned*)(smem + FA_TOTAL + (kt & 1) * FB_STAGE);

#pragma unroll
        for (int kk = 0; kk < 32; kk += 8) {
            unsigned a[4][4], b[8][2];
#pragma unroll
            for (int mi = 0; mi < 4; mi++) {
                int rr = wm + mi * 16;
                a[mi][0] = As[(rr + g)     * SMSTRIDE + kk + tg];
                a[mi][1] = As[(rr + g + 8) * SMSTRIDE + kk + tg];
                a[mi][2] = As[(rr + g)     * SMSTRIDE + kk + tg + 4];
                a[mi][3] = As[(rr + g + 8) * SMSTRIDE + kk + tg + 4];
            }
#pragma unroll
            for (int ni = 0; ni < 8; ni++) {
                int cc = wn + ni * 8 + g;
                b[ni][0] = Bs[cc * SMSTRIDE + kk + tg];
                b[ni][1] = Bs[cc * SMSTRIDE + kk + tg + 4];
            }
#pragma unroll
            for (int mi = 0; mi < 4; mi++)
#pragma unroll
                for (int ni = 0; ni < 8; ni++) {
                    asm volatile(
                        "mma.sync.aligned.m16n8k8.row.col.f32.tf32.tf32.f32 "
                        "{%0,%1,%2,%3}, {%4,%5,%6,%7}, {%8,%9}, {%0,%1,%2,%3};"
                        : "+f"(acc[mi][ni][0]), "+f"(acc[mi][ni][1]),
                          "+f"(acc[mi][ni][2]), "+f"(acc[mi][ni][3])
                        : "r"(a[mi][0]), "r"(a[mi][1]),
                          "r"(a[mi][2]), "r"(a[mi][3]),
                          "r"(b[ni][0]), "r"(b[ni][1]));
                }
        }
        __syncthreads();
        if (kt + 2 < 8) issueB_f(sbase, kt & 1, kt + 2, tid);
        cp_commit();
    }

#pragma unroll
    for (int mi = 0; mi < 4; mi++) {
        size_t row0 = rowBase + wm + mi * 16 + g;
#pragma unroll
        for (int ni = 0; ni < 8; ni++) {
            int col = wn + ni * 8 + 2 * tg;
            float v0 = tanhf(acc[mi][ni][0] + g_beff[col]);
            float v1 = tanhf(acc[mi][ni][1] + g_beff[col + 1]);
            float v2 = tanhf(acc[mi][ni][2] + g_beff[col]);
            float v3 = tanhf(acc[mi][ni][3] + g_beff[col + 1]);
            *(float2*)&out[row0 * 256 + col]       = make_float2(v0, v1);
            *(float2*)&out[(row0 + 8) * 256 + col] = make_float2(v2, v3);
        }
    }
}

// ---------------------------------------------------------------------------
// Launch (6 kernels; fused_final at launch index 5 for ncu -s 5)
// ---------------------------------------------------------------------------
extern "C" void kernel_launch(void* const* d_in, const int* in_sizes, int n_in,
                              void* d_out, int out_size) {
    const float* x     = (const float*)d_in[0];
    const float* gamma = (const float*)d_in[1];
    const float* beta  = (const float*)d_in[2];
    const float* W1    = (const float*)d_in[3];
    const float* W2    = (const float*)d_in[5];
    const float* Wf    = (const float*)d_in[7];
    const float* b1    = (const float*)d_in[4];
    const float* b2    = (const float*)d_in[6];
    const float* bf    = (const float*)d_in[8];

    float* out = (float*)d_out;
    float* raw = out + (size_t)NROWS * DIM;

    float *w2t, *wfr, *wpart;
    cudaGetSymbolAddress((void**)&w2t,   g_w2t);
    cudaGetSymbolAddress((void**)&wfr,   g_wfr);
    cudaGetSymbolAddress((void**)&wpart, g_wpart);

    cudaFuncSetAttribute(gemm_splitk,
                         cudaFuncAttributeMaxDynamicSharedMemorySize, GEMM_SMEM);
    cudaFuncSetAttribute(fused_final,
                         cudaFuncAttributeMaxDynamicSharedMemorySize, F_SMEM);

    // 0: bn partials + W2 transpose/round + Wf round + t2
    prep<<<800, 256>>>(x, W2, Wf, b1, b2);
    // 1: T1 partials = Wf @ W2 (split-K 16): M=256, N=512, K=2048
    gemm_splitk<<<dim3(2, 2, 16), 256, GEMM_SMEM>>>(wfr, w2t, wpart,
                                                    512, 2048, 128);
    // 2: reduce partials -> T1 fp32
    t1_reduce<<<32, 256>>>();
    // 3: beff
    bias_beff<<<32, 256>>>(Wf, bf);
    // 4: Weff = T1 @ W1 (FFMA) + round, plus bn_final
    weff_bnfinal<<<65, 256>>>(W1, gamma, beta);
    // 5: fused normalize + raw + GEMM + tanh
    fused_final<<<NROWS / 128, 256, F_SMEM>>>(x, raw, out);
}

// round 7
// speedup vs baseline: 10.4920x; 1.2064x over previous
#include <cuda_runtime.h>
#include <math.h>
#include <cstdint>

#define NROWS 65536
#define DIM   256
#define H1    512
#define H2    2048

// ---------------------------------------------------------------------------
// Device scratch (allocation-free rule)
// ---------------------------------------------------------------------------
__device__ __align__(16) float g_partS[256 * 256];
__device__ __align__(16) float g_partQ[256 * 256];
__device__ __align__(16) float g_scale[DIM];
__device__ __align__(16) float g_shift[DIM];
__device__ __align__(16) float g_w2t[H1 * H2];        // W2^T rounded [512,2048]
__device__ __align__(16) float g_wfr[DIM * H2];       // Wf rounded   [256,2048]
__device__ __align__(16) float g_t2[H2];              // W2@b1 + b2
__device__ __align__(16) float g_beff[DIM];           // Wf@t2 + bf
__device__ __align__(16) float g_t1[DIM * H1];        // T1 = Wf@W2 fp32 (atomic acc)
__device__ __align__(16) float g_weff[DIM * DIM];     // Wf@W2@W1 rounded [256,256]

// ---------------------------------------------------------------------------
// Helpers
// ---------------------------------------------------------------------------
__device__ __forceinline__ unsigned f2tf(float f) {
    unsigned u;
    asm("cvt.rna.tf32.f32 %0, %1;" : "=r"(u) : "f"(f));
    return u;
}
__device__ __forceinline__ float tanh_ap(float x) {
    float r;
    asm("tanh.approx.f32 %0, %1;" : "=f"(r) : "f"(x));
    return r;
}
__device__ __forceinline__ uint32_t smem_u32(const void* p) {
    uint32_t a;
    asm("{ .reg .u64 t; cvta.to.shared.u64 t, %1; cvt.u32.u64 %0, t; }"
        : "=r"(a) : "l"(p));
    return a;
}
__device__ __forceinline__ void cp16(uint32_t dst, const void* src) {
    asm volatile("cp.async.cg.shared.global [%0], [%1], 16;"
                 :: "r"(dst), "l"(src));
}
__device__ __forceinline__ void cp_commit() {
    asm volatile("cp.async.commit_group;" ::: "memory");
}
template <int N>
__device__ __forceinline__ void cp_wait() {
    asm volatile("cp.async.wait_group %0;" :: "n"(N) : "memory");
}

// ---------------------------------------------------------------------------
// K0 prep (808 blocks):
//   [0,256)    bn partial sums over x
//   [256,512)  W2 transpose + tf32 round -> g_w2t
//   [512,544)  round Wf -> g_wfr
//   [544,800)  t2 = W2@b1 + b2
//   [800,808)  zero g_t1
// ---------------------------------------------------------------------------
__global__ __launch_bounds__(256)
void prep(const float* __restrict__ x, const float* __restrict__ W2,
          const float* __restrict__ Wf, const float* __restrict__ b1,
          const float* __restrict__ b2) {
    __shared__ float ts[64][65];
    int bx = blockIdx.x, tid = threadIdx.x;
    if (bx < 256) {
        const float* xp = x + (size_t)bx * 256 * DIM + tid;
        float s = 0.f, q = 0.f;
#pragma unroll 8
        for (int r = 0; r < 256; r++) {
            float v = xp[(size_t)r * DIM];
            s += v; q += v * v;
        }
        g_partS[bx * 256 + tid] = s;
        g_partQ[bx * 256 + tid] = q;
    } else if (bx < 512) {
        int b2i = bx - 256;
        int i0 = (b2i & 31) * 64;
        int j0 = (b2i >> 5) * 64;
#pragma unroll
        for (int t = 0; t < 16; t++) {
            int e = tid + t * 256;
            int r = e >> 6, c = e & 63;
            ts[r][c] = W2[(size_t)(i0 + r) * H1 + j0 + c];
        }
        __syncthreads();
#pragma unroll
        for (int t = 0; t < 16; t++) {
            int e = tid + t * 256;
            int r = e >> 6, c = e & 63;
            g_w2t[(size_t)(j0 + r) * H2 + i0 + c] =
                __uint_as_float(f2tf(ts[c][r]));
        }
    } else if (bx < 544) {
        int base = (bx - 512) * 4096;
#pragma unroll
        for (int t = 0; t < 16; t++) {
            int i = base + tid + t * 256;
            float4 v = ((const float4*)Wf)[i];
            v.x = __uint_as_float(f2tf(v.x));
            v.y = __uint_as_float(f2tf(v.y));
            v.z = __uint_as_float(f2tf(v.z));
            v.w = __uint_as_float(f2tf(v.w));
            ((float4*)g_wfr)[i] = v;
        }
    } else if (bx < 800) {
        int w = tid >> 5, lane = tid & 31;
        int row = (bx - 544) * 8 + w;
        const float* wr = W2 + (size_t)row * H1;
        float s = 0.f;
#pragma unroll
        for (int i = 0; i < H1 / 32; i++)
            s += wr[lane + i * 32] * b1[lane + i * 32];
#pragma unroll
        for (int o = 16; o; o >>= 1) s += __shfl_xor_sync(~0u, s, o);
        if (lane == 0) g_t2[row] = s + b2[row];
    } else {
        int base = (bx - 800) * 4096;
        float4 z = make_float4(0.f, 0.f, 0.f, 0.f);
#pragma unroll
        for (int t = 0; t < 16; t++)
            ((float4*)g_t1)[base + tid + t * 256] = z;
    }
}

// ---------------------------------------------------------------------------
// K1 wchain (65 blocks, GEMM_SMEM dyn smem):
//   [0,32)  split-K(8) tf32 GEMM: T1 += Wf @ W2^T  (atomicAdd epilogue)
//   [32,64) beff = Wf@t2 + bf
//   [64]    bn_final -> g_scale/g_shift
// ---------------------------------------------------------------------------
#define SMSTRIDE   36
#define ROWBYTES   (SMSTRIDE * 4)
#define A_BYTES    (128 * ROWBYTES)
#define B_BYTES    (256 * ROWBYTES)
#define STAGE_B    (A_BYTES + B_BYTES)
#define STAGES     3
#define GEMM_SMEM  (STAGES * STAGE_B)

__device__ __forceinline__ void issue_tile(const float* aPtr, const float* bPtr,
                                           uint32_t sA, uint32_t sB,
                                           int kOff, int K) {
#pragma unroll
    for (int j = 0; j < 4; j++)
        cp16(sA + j * 32 * ROWBYTES, aPtr + (size_t)j * 32 * K + kOff);
#pragma unroll
    for (int j = 0; j < 8; j++)
        cp16(sB + j * 32 * ROWBYTES, bPtr + (size_t)j * 32 * K + kOff);
}

__global__ __launch_bounds__(256, 1)
void wchain(const float* __restrict__ W2, const float* __restrict__ Wf,
            const float* __restrict__ bf, const float* __restrict__ gamma,
            const float* __restrict__ beta) {
    extern __shared__ char smem[];
    const int bx = blockIdx.x;
    const int tid = threadIdx.x;

    if (bx >= 64) {               // bn_final
        float s = 0.f, q = 0.f;
#pragma unroll 4
        for (int b = 0; b < 256; b++) {
            s += g_partS[b * 256 + tid];
            q += g_partQ[b * 256 + tid];
        }
        const float inv = 1.0f / (float)NROWS;
        float mu  = s * inv;
        float var = q * inv - mu * mu;
        float sc  = gamma[tid] * rsqrtf(var + 1e-5f);
        g_scale[tid] = sc;
        g_shift[tid] = beta[tid] - mu * sc;
        return;
    }
    if (bx >= 32) {               // beff
        int w = tid >> 5, lane = tid & 31;
        int row = (bx - 32) * 8 + w;
        const float* wr = Wf + (size_t)row * H2;
        float s = 0.f;
#pragma unroll
        for (int i = 0; i < H2 / 32; i++)
            s += wr[lane + i * 32] * g_t2[lane + i * 32];
#pragma unroll
        for (int o = 16; o; o >>= 1) s += __shfl_xor_sync(~0u, s, o);
        if (lane == 0) g_beff[row] = s + bf[row];
        return;
    }

    // ---- split-K GEMM: A=g_wfr [256,2048], W=g_w2t [512,2048], K slice 256 ----
    const uint32_t sbase = smem_u32(smem);
    const int lane = tid & 31;
    const int g    = lane >> 2;
    const int tg   = lane & 3;
    const int wid  = tid >> 5;
    const int wm   = (wid & 1) * 64;
    const int wn   = (wid >> 1) * 64;

    const int xx = bx & 1, yy = (bx >> 1) & 1, z = bx >> 2;
    const int K = H2, kloop = 256, T = kloop >> 5;
    const float* A = g_wfr + z * kloop;
    const float* W = g_w2t + z * kloop;

    const size_t rowBase = (size_t)yy * 128;
    const size_t colBase = (size_t)xx * 256;

    const int r0 = tid >> 3;
    const int c0 = tid & 7;
    const float* aPtr = A + (rowBase + r0) * (size_t)K + c0 * 4;
    const float* bPtr = W + (colBase + r0) * (size_t)K + c0 * 4;
    const uint32_t sAo = r0 * ROWBYTES + c0 * 16;
    const uint32_t sBo = A_BYTES + r0 * ROWBYTES + c0 * 16;

    float acc[4][8][4];
#pragma unroll
    for (int mi = 0; mi < 4; mi++)
#pragma unroll
        for (int ni = 0; ni < 8; ni++)
#pragma unroll
            for (int k = 0; k < 4; k++) acc[mi][ni][k] = 0.f;

    issue_tile(aPtr, bPtr, sbase + sAo, sbase + sBo, 0, K);
    cp_commit();
    issue_tile(aPtr, bPtr, sbase + STAGE_B + sAo, sbase + STAGE_B + sBo, 32, K);
    cp_commit();

    for (int kt = 0; kt < T; kt++) {
        cp_wait<1>();
        __syncthreads();
        if (kt + 2 < T) {
            uint32_t sb2 = sbase + ((kt + 2) % STAGES) * STAGE_B;
            issue_tile(aPtr, bPtr, sb2 + sAo, sb2 + sBo, (kt + 2) * 32, K);
        }
        cp_commit();

        const unsigned* As = (const unsigned*)(smem + (kt % STAGES) * STAGE_B);
        const unsigned* Bs = (const unsigned*)(smem + (kt % STAGES) * STAGE_B + A_BYTES);
#pragma unroll
        for (int kk = 0; kk < 32; kk += 8) {
            unsigned a[4][4], b[8][2];
#pragma unroll
            for (int mi = 0; mi < 4; mi++) {
                int rr = wm + mi * 16;
                a[mi][0] = As[(rr + g)     * SMSTRIDE + kk + tg];
                a[mi][1] = As[(rr + g + 8) * SMSTRIDE + kk + tg];
                a[mi][2] = As[(rr + g)     * SMSTRIDE + kk + tg + 4];
                a[mi][3] = As[(rr + g + 8) * SMSTRIDE + kk + tg + 4];
            }
#pragma unroll
            for (int ni = 0; ni < 8; ni++) {
                int cc = wn + ni * 8 + g;
                b[ni][0] = Bs[cc * SMSTRIDE + kk + tg];
                b[ni][1] = Bs[cc * SMSTRIDE + kk + tg + 4];
            }
#pragma unroll
            for (int mi = 0; mi < 4; mi++)
#pragma unroll
                for (int ni = 0; ni < 8; ni++) {
                    asm volatile(
                        "mma.sync.aligned.m16n8k8.row.col.f32.tf32.tf32.f32 "
                        "{%0,%1,%2,%3}, {%4,%5,%6,%7}, {%8,%9}, {%0,%1,%2,%3};"
                        : "+f"(acc[mi][ni][0]), "+f"(acc[mi][ni][1]),
                          "+f"(acc[mi][ni][2]), "+f"(acc[mi][ni][3])
                        : "r"(a[mi][0]), "r"(a[mi][1]),
                          "r"(a[mi][2]), "r"(a[mi][3]),
                          "r"(b[ni][0]), "r"(b[ni][1]));
                }
        }
    }

#pragma unroll
    for (int mi = 0; mi < 4; mi++) {
        int row0 = (int)rowBase + wm + mi * 16 + g;
#pragma unroll
        for (int ni = 0; ni < 8; ni++) {
            int col = (int)colBase + wn + ni * 8 + 2 * tg;
            atomicAdd(&g_t1[row0 * H1 + col],           acc[mi][ni][0]);
            atomicAdd(&g_t1[row0 * H1 + col + 1],       acc[mi][ni][1]);
            atomicAdd(&g_t1[(row0 + 8) * H1 + col],     acc[mi][ni][2]);
            atomicAdd(&g_t1[(row0 + 8) * H1 + col + 1], acc[mi][ni][3]);
        }
    }
}

// ---------------------------------------------------------------------------
// K2: Weff = T1 @ W1 (fp32 FFMA, 32x32 tiles, 64 blocks, reg-prefetched) + round
// Shared tiles padded to 36 floats/row (144B) so float4 LDS/STS stay 16B-aligned.
// ---------------------------------------------------------------------------
__global__ __launch_bounds__(256)
void weff_k(const float* __restrict__ W1) {
    __shared__ float As[32][36], Bs[32][36];
    int tid = threadIdx.x;
    int i0 = (blockIdx.x >> 3) * 32, j0 = (blockIdx.x & 7) * 32;
    int ty = tid >> 4, tx = tid & 15;
    int lr = tid >> 3, lc4 = (tid & 7) * 4;
    float a00 = 0.f, a01 = 0.f, a10 = 0.f, a11 = 0.f;

    float4 ra = *(const float4*)(&g_t1[(i0 + lr) * H1 + lc4]);
    float4 rb = *(const float4*)(&W1[(size_t)lr * DIM + j0 + lc4]);

    for (int kb = 0; kb < H1; kb += 32) {
        *(float4*)(&As[lr][lc4]) = ra;
        *(float4*)(&Bs[lr][lc4]) = rb;
        __syncthreads();
        if (kb + 32 < H1) {
            ra = *(const float4*)(&g_t1[(i0 + lr) * H1 + kb + 32 + lc4]);
            rb = *(const float4*)(&W1[(size_t)(kb + 32 + lr) * DIM + j0 + lc4]);
        }
#pragma unroll
        for (int k = 0; k < 32; k++) {
            float x0 = As[ty * 2][k],     x1 = As[ty * 2 + 1][k];
            float y0 = Bs[k][tx * 2],     y1 = Bs[k][tx * 2 + 1];
            a00 = fmaf(x0, y0, a00); a01 = fmaf(x0, y1, a01);
            a10 = fmaf(x1, y0, a10); a11 = fmaf(x1, y1, a11);
        }
        __syncthreads();
    }
    int r0 = i0 + ty * 2, c0 = j0 + tx * 2;
    g_weff[r0 * DIM + c0]           = __uint_as_float(f2tf(a00));
    g_weff[r0 * DIM + c0 + 1]       = __uint_as_float(f2tf(a01));
    g_weff[(r0 + 1) * DIM + c0]     = __uint_as_float(f2tf(a10));
    g_weff[(r0 + 1) * DIM + c0 + 1] = __uint_as_float(f2tf(a11));
}

// ---------------------------------------------------------------------------
// K3 fused final, chunk-pipelined:
//   MMA(chunk kt) overlaps x-load/tanh/pack of chunk kt+1 + cp.async of B kt+2.
// ---------------------------------------------------------------------------
#define FA_STAGE 18432
#define FB_STAGE 36864
#define FA_TOTAL (8 * FA_STAGE)
#define F_SMEM   (FA_TOTAL + 2 * FB_STAGE)

__device__ __forceinline__ void issueB_f(uint32_t sbase, int slot, int kt, int tid) {
#pragma unroll
    for (int j = 0; j < 8; j++) {
        int r = (tid >> 3) + j * 32;
        cp16(sbase + FA_TOTAL + slot * FB_STAGE + r * ROWBYTES + (tid & 7) * 16,
             g_weff + r * 256 + kt * 32 + (tid & 7) * 4);
    }
}

__global__ __launch_bounds__(256, 1)
void fused_final(const float* __restrict__ x, float* __restrict__ raw,
                 float* __restrict__ out) {
    extern __shared__ char smem[];
    const uint32_t sbase = smem_u32(smem);
    const int tid  = threadIdx.x;
    const int lane = tid & 31;
    const int g    = lane >> 2;
    const int tg   = lane & 3;
    const int wid  = tid >> 5;
    const int wm   = (wid & 1) * 64;
    const int wn   = (wid >> 1) * 64;
    const size_t rowBase = (size_t)blockIdx.x * 128;

    issueB_f(sbase, 0, 0, tid);
    cp_commit();
    issueB_f(sbase, 1, 1, tid);
    cp_commit();

    const int cf = tid & 7;
    const float* xp[4];
    float* rp[4];
    uint32_t so[4];
#pragma unroll
    for (int j = 0; j < 4; j++) {
        int r = (tid >> 3) + j * 32;
        xp[j] = x   + (rowBase + r) * 256 + cf * 4;
        rp[j] = raw + (rowBase + r) * 256 + cf * 4;
        so[j] = r * ROWBYTES + cf * 16;
    }

    // generate chunk 0
    float4 nv[4];
#pragma unroll
    for (int j = 0; j < 4; j++) nv[j] = *(const float4*)(xp[j]);
    {
        float4 sc = ((const float4*)g_scale)[cf];
        float4 sh = ((const float4*)g_shift)[cf];
#pragma unroll
        for (int j = 0; j < 4; j++) {
            float4 xn;
            xn.x = fmaf(nv[j].x, sc.x, sh.x);
            xn.y = fmaf(nv[j].y, sc.y, sh.y);
            xn.z = fmaf(nv[j].z, sc.z, sh.z);
            xn.w = fmaf(nv[j].w, sc.w, sh.w);
            float4 t;
            t.x = tanh_ap(xn.x); t.y = tanh_ap(xn.y);
            t.z = tanh_ap(xn.z); t.w = tanh_ap(xn.w);
            *(float4*)(rp[j]) = t;
            uint4 rb;
            rb.x = f2tf(xn.x); rb.y = f2tf(xn.y);
            rb.z = f2tf(xn.z); rb.w = f2tf(xn.w);
            *(uint4*)(smem + so[j]) = rb;
        }
    }

    float acc[4][8][4];
#pragma unroll
    for (int mi = 0; mi < 4; mi++)
#pragma unroll
        for (int ni = 0; ni < 8; ni++)
#pragma unroll
            for (int k = 0; k < 4; k++) acc[mi][ni][k] = 0.f;

    for (int kt = 0; kt < 8; kt++) {
        if (kt < 7) {
#pragma unroll
            for (int j = 0; j < 4; j++)
                nv[j] = *(const float4*)(xp[j] + (kt + 1) * 32);
        }
        cp_wait<1>();
        __syncthreads();

        const unsigned* As = (const unsigned*)(smem + kt * FA_STAGE);
        const unsigned* Bs = (const unsigned*)(smem + FA_TOTAL + (kt & 1) * FB_STAGE);
#pragma unroll
        for (int kk = 0; kk < 32; kk += 8) {
            unsigned a[4][4], b[8][2];
#pragma unroll
            for (int mi = 0; mi < 4; mi++) {
                int rr = wm + mi * 16;
                a[mi][0] = As[(rr + g)     * SMSTRIDE + kk + tg];
                a[mi][1] = As[(rr + g + 8) * SMSTRIDE + kk + tg];
                a[mi][2] = As[(rr + g)     * SMSTRIDE + kk + tg + 4];
                a[mi][3] = As[(rr + g + 8) * SMSTRIDE + kk + tg + 4];
            }
#pragma unroll
            for (int ni = 0; ni < 8; ni++) {
                int cc = wn + ni * 8 + g;
                b[ni][0] = Bs[cc * SMSTRIDE + kk + tg];
                b[ni][1] = Bs[cc * SMSTRIDE + kk + tg + 4];
            }
#pragma unroll
            for (int mi = 0; mi < 4; mi++)
#pragma unroll
                for (int ni = 0; ni < 8; ni++) {
                    asm volatile(
                        "mma.sync.aligned.m16n8k8.row.col.f32.tf32.tf32.f32 "
                        "{%0,%1,%2,%3}, {%4,%5,%6,%7}, {%8,%9}, {%0,%1,%2,%3};"
                        : "+f"(acc[mi][ni][0]), "+f"(acc[mi][ni][1]),
                          "+f"(acc[mi][ni][2]), "+f"(acc[mi][ni][3])
                        : "r"(a[mi][0]), "r"(a[mi][1]),
                          "r"(a[mi][2]), "r"(a[mi][3]),
                          "r"(b[ni][0]), "r"(b[ni][1]));
                }
        }

        if (kt < 7) {
            float4 sc = ((const float4*)g_scale)[(kt + 1) * 8 + cf];
            float4 sh = ((const float4*)g_shift)[(kt + 1) * 8 + cf];
#pragma unroll
            for (int j = 0; j < 4; j++) {
                float4 xn;
                xn.x = fmaf(nv[j].x, sc.x, sh.x);
                xn.y = fmaf(nv[j].y, sc.y, sh.y);
                xn.z = fmaf(nv[j].z, sc.z, sh.z);
                xn.w = fmaf(nv[j].w, sc.w, sh.w);
                float4 t;
                t.x = tanh_ap(xn.x); t.y = tanh_ap(xn.y);
                t.z = tanh_ap(xn.z); t.w = tanh_ap(xn.w);
                *(float4*)(rp[j] + (kt + 1) * 32) = t;
                uint4 rb;
                rb.x = f2tf(xn.x); rb.y = f2tf(xn.y);
                rb.z = f2tf(xn.z); rb.w = f2tf(xn.w);
                *(uint4*)(smem + so[j] + (kt + 1) * FA_STAGE) = rb;
            }
        }
        __syncthreads();
        if (kt + 2 < 8) issueB_f(sbase, kt & 1, kt + 2, tid);
        cp_commit();
    }

#pragma unroll
    for (int mi = 0; mi < 4; mi++) {
        size_t row0 = rowBase + wm + mi * 16 + g;
#pragma unroll
        for (int ni = 0; ni < 8; ni++) {
            int col = wn + ni * 8 + 2 * tg;
            float v0 = tanh_ap(acc[mi][ni][0] + g_beff[col]);
            float v1 = tanh_ap(acc[mi][ni][1] + g_beff[col + 1]);
            float v2 = tanh_ap(acc[mi][ni][2] + g_beff[col]);
            float v3 = tanh_ap(acc[mi][ni][3] + g_beff[col + 1]);
            *(float2*)&out[row0 * 256 + col]       = make_float2(v0, v1);
            *(float2*)&out[(row0 + 8) * 256 + col] = make_float2(v2, v3);
        }
    }
}

// ---------------------------------------------------------------------------
// Launch (4 kernels)
// ---------------------------------------------------------------------------
extern "C" void kernel_launch(void* const* d_in, const int* in_sizes, int n_in,
                              void* d_out, int out_size) {
    const float* x     = (const float*)d_in[0];
    const float* gamma = (const float*)d_in[1];
    const float* beta  = (const float*)d_in[2];
    const float* W1    = (const float*)d_in[3];
    const float* b1    = (const float*)d_in[4];
    const float* W2    = (const float*)d_in[5];
    const float* b2    = (const float*)d_in[6];
    const float* Wf    = (const float*)d_in[7];
    const float* bf    = (const float*)d_in[8];

    float* out = (float*)d_out;
    float* raw = out + (size_t)NROWS * DIM;

    cudaFuncSetAttribute(wchain,
                         cudaFuncAttributeMaxDynamicSharedMemorySize, GEMM_SMEM);
    cudaFuncSetAttribute(fused_final,
                         cudaFuncAttributeMaxDynamicSharedMemorySize, F_SMEM);

    prep<<<808, 256>>>(x, W2, Wf, b1, b2);
    wchain<<<65, 256, GEMM_SMEM>>>(W2, Wf, bf, gamma, beta);
    weff_k<<<64, 256>>>(W1);
    fused_final<<<NROWS / 128, 256, F_SMEM>>>(x, raw, out);
}

// round 8
// speedup vs baseline: 12.2076x; 1.1635x over previous
#include <cuda_runtime.h>
#include <math.h>
#include <cstdint>

#define NROWS 65536
#define DIM   256
#define H1    512
#define H2    2048

// ---------------------------------------------------------------------------
// Device scratch (allocation-free rule)
// ---------------------------------------------------------------------------
__device__ __align__(16) float g_partS[256 * 256];
__device__ __align__(16) float g_partQ[256 * 256];
__device__ __align__(16) float g_scale[DIM];
__device__ __align__(16) float g_shift[DIM];
__device__ __align__(16) float g_w2t[H1 * H2];        // W2^T rounded [512,2048]
__device__ __align__(16) float g_wfr[DIM * H2];       // Wf rounded   [256,2048]
__device__ __align__(16) float g_t2[H2];              // W2@b1 + b2
__device__ __align__(16) float g_beff[DIM];           // Wf@t2 + bf
__device__ __align__(16) float g_t1[DIM * H1];        // T1 = Wf@W2 fp32 (atomic acc)
__device__ __align__(16) float g_weff[DIM * DIM];     // Wf@W2@W1 rounded [256,256]

// ---------------------------------------------------------------------------
// Helpers
// ---------------------------------------------------------------------------
__device__ __forceinline__ unsigned f2tf(float f) {
    unsigned u;
    asm("cvt.rna.tf32.f32 %0, %1;" : "=r"(u) : "f"(f));
    return u;
}
__device__ __forceinline__ float tanh_ap(float x) {
    float r;
    asm("tanh.approx.f32 %0, %1;" : "=f"(r) : "f"(x));
    return r;
}
__device__ __forceinline__ uint32_t smem_u32(const void* p) {
    uint32_t a;
    asm("{ .reg .u64 t; cvta.to.shared.u64 t, %1; cvt.u32.u64 %0, t; }"
        : "=r"(a) : "l"(p));
    return a;
}
__device__ __forceinline__ void cp16(uint32_t dst, const void* src) {
    asm volatile("cp.async.cg.shared.global [%0], [%1], 16;"
                 :: "r"(dst), "l"(src));
}
__device__ __forceinline__ void cp_commit() {
    asm volatile("cp.async.commit_group;" ::: "memory");
}
template <int N>
__device__ __forceinline__ void cp_wait() {
    asm volatile("cp.async.wait_group %0;" :: "n"(N) : "memory");
}

// ---------------------------------------------------------------------------
// K0 prep (552 blocks) — weights only:
//   [0,256)   W2 transpose + tf32 round -> g_w2t
//   [256,288) round Wf -> g_wfr
//   [288,544) t2 = W2@b1 + b2
//   [544,552) zero g_t1
// ---------------------------------------------------------------------------
__global__ __launch_bounds__(256)
void prep(const float* __restrict__ W2, const float* __restrict__ Wf,
          const float* __restrict__ b1, const float* __restrict__ b2) {
    __shared__ float ts[64][65];
    int bx = blockIdx.x, tid = threadIdx.x;
    if (bx < 256) {
        int i0 = (bx & 31) * 64;          // over 2048
        int j0 = (bx >> 5) * 64;          // over 512
#pragma unroll
        for (int t = 0; t < 16; t++) {
            int e = tid + t * 256;
            int r = e >> 6, c = e & 63;
            ts[r][c] = W2[(size_t)(i0 + r) * H1 + j0 + c];
        }
        __syncthreads();
#pragma unroll
        for (int t = 0; t < 16; t++) {
            int e = tid + t * 256;
            int r = e >> 6, c = e & 63;
            g_w2t[(size_t)(j0 + r) * H2 + i0 + c] =
                __uint_as_float(f2tf(ts[c][r]));
        }
    } else if (bx < 288) {
        int base = (bx - 256) * 4096;
#pragma unroll
        for (int t = 0; t < 16; t++) {
            int i = base + tid + t * 256;
            float4 v = ((const float4*)Wf)[i];
            v.x = __uint_as_float(f2tf(v.x));
            v.y = __uint_as_float(f2tf(v.y));
            v.z = __uint_as_float(f2tf(v.z));
            v.w = __uint_as_float(f2tf(v.w));
            ((float4*)g_wfr)[i] = v;
        }
    } else if (bx < 544) {
        int w = tid >> 5, lane = tid & 31;
        int row = (bx - 288) * 8 + w;
        const float* wr = W2 + (size_t)row * H1;
        float s = 0.f;
#pragma unroll
        for (int i = 0; i < H1 / 32; i++)
            s += wr[lane + i * 32] * b1[lane + i * 32];
#pragma unroll
        for (int o = 16; o; o >>= 1) s += __shfl_xor_sync(~0u, s, o);
        if (lane == 0) g_t2[row] = s + b2[row];
    } else {
        int base = (bx - 544) * 4096;
        float4 z = make_float4(0.f, 0.f, 0.f, 0.f);
#pragma unroll
        for (int t = 0; t < 16; t++)
            ((float4*)g_t1)[base + tid + t * 256] = z;
    }
}

// ---------------------------------------------------------------------------
// K1 wchain (320 blocks, GEMM_SMEM dyn smem):
//   [0,32)   split-K(8) tf32 GEMM: T1 += Wf @ W2^T  (atomicAdd epilogue)
//   [32,64)  beff = Wf@t2 + bf
//   [64,320) bn x-scan: block handles 256 rows, float4, intra-block reduce
// ---------------------------------------------------------------------------
#define SMSTRIDE   36
#define ROWBYTES   (SMSTRIDE * 4)
#define A_BYTES    (128 * ROWBYTES)
#define B_BYTES    (256 * ROWBYTES)
#define STAGE_B    (A_BYTES + B_BYTES)
#define STAGES     3
#define GEMM_SMEM  (STAGES * STAGE_B)

__device__ __forceinline__ void issue_tile(const float* aPtr, const float* bPtr,
                                           uint32_t sA, uint32_t sB,
                                           int kOff, int K) {
#pragma unroll
    for (int j = 0; j < 4; j++)
        cp16(sA + j * 32 * ROWBYTES, aPtr + (size_t)j * 32 * K + kOff);
#pragma unroll
    for (int j = 0; j < 8; j++)
        cp16(sB + j * 32 * ROWBYTES, bPtr + (size_t)j * 32 * K + kOff);
}

__global__ __launch_bounds__(256, 1)
void wchain(const float* __restrict__ x, const float* __restrict__ Wf,
            const float* __restrict__ bf) {
    extern __shared__ char smem[];
    const int bx = blockIdx.x;
    const int tid = threadIdx.x;

    if (bx >= 64) {               // ---- bn x-scan, 256 rows per block ----
        __shared__ float4 rs[4][64], rq[4][64];
        int bxs = bx - 64;
        int rg = tid >> 6;                 // 0..3 row groups
        int tc = tid & 63;                 // float4 column
        const float4* xp = (const float4*)(x + (size_t)(bxs * 256 + rg * 64) * DIM) + tc;
        float4 s = make_float4(0.f, 0.f, 0.f, 0.f);
        float4 q = make_float4(0.f, 0.f, 0.f, 0.f);
#pragma unroll 8
        for (int i = 0; i < 64; i++) {
            float4 v = xp[(size_t)i * 64];
            s.x += v.x; s.y += v.y; s.z += v.z; s.w += v.w;
            q.x += v.x * v.x; q.y += v.y * v.y;
            q.z += v.z * v.z; q.w += v.w * v.w;
        }
        rs[rg][tc] = s; rq[rg][tc] = q;
        __syncthreads();
        if (rg == 0) {
#pragma unroll
            for (int z = 1; z < 4; z++) {
                float4 a = rs[z][tc], b = rq[z][tc];
                s.x += a.x; s.y += a.y; s.z += a.z; s.w += a.w;
                q.x += b.x; q.y += b.y; q.z += b.z; q.w += b.w;
            }
            ((float4*)(g_partS + bxs * 256))[tc] = s;
            ((float4*)(g_partQ + bxs * 256))[tc] = q;
        }
        return;
    }
    if (bx >= 32) {               // ---- beff ----
        int w = tid >> 5, lane = tid & 31;
        int row = (bx - 32) * 8 + w;
        const float* wr = Wf + (size_t)row * H2;
        float s = 0.f;
#pragma unroll
        for (int i = 0; i < H2 / 32; i++)
            s += wr[lane + i * 32] * g_t2[lane + i * 32];
#pragma unroll
        for (int o = 16; o; o >>= 1) s += __shfl_xor_sync(~0u, s, o);
        if (lane == 0) g_beff[row] = s + bf[row];
        return;
    }

    // ---- split-K GEMM: A=g_wfr [256,2048], W=g_w2t [512,2048], K slice 256 ----
    const uint32_t sbase = smem_u32(smem);
    const int lane = tid & 31;
    const int g    = lane >> 2;
    const int tg   = lane & 3;
    const int wid  = tid >> 5;
    const int wm   = (wid & 1) * 64;
    const int wn   = (wid >> 1) * 64;

    const int xx = bx & 1, yy = (bx >> 1) & 1, z = bx >> 2;
    const int K = H2, kloop = 256, T = kloop >> 5;
    const float* A = g_wfr + z * kloop;
    const float* W = g_w2t + z * kloop;

    const size_t rowBase = (size_t)yy * 128;
    const size_t colBase = (size_t)xx * 256;

    const int r0 = tid >> 3;
    const int c0 = tid & 7;
    const float* aPtr = A + (rowBase + r0) * (size_t)K + c0 * 4;
    const float* bPtr = W + (colBase + r0) * (size_t)K + c0 * 4;
    const uint32_t sAo = r0 * ROWBYTES + c0 * 16;
    const uint32_t sBo = A_BYTES + r0 * ROWBYTES + c0 * 16;

    float acc[4][8][4];
#pragma unroll
    for (int mi = 0; mi < 4; mi++)
#pragma unroll
        for (int ni = 0; ni < 8; ni++)
#pragma unroll
            for (int k = 0; k < 4; k++) acc[mi][ni][k] = 0.f;

    issue_tile(aPtr, bPtr, sbase + sAo, sbase + sBo, 0, K);
    cp_commit();
    issue_tile(aPtr, bPtr, sbase + STAGE_B + sAo, sbase + STAGE_B + sBo, 32, K);
    cp_commit();

    for (int kt = 0; kt < T; kt++) {
        cp_wait<1>();
        __syncthreads();
        if (kt + 2 < T) {
            uint32_t sb2 = sbase + ((kt + 2) % STAGES) * STAGE_B;
            issue_tile(aPtr, bPtr, sb2 + sAo, sb2 + sBo, (kt + 2) * 32, K);
        }
        cp_commit();

        const unsigned* As = (const unsigned*)(smem + (kt % STAGES) * STAGE_B);
        const unsigned* Bs = (const unsigned*)(smem + (kt % STAGES) * STAGE_B + A_BYTES);
#pragma unroll
        for (int kk = 0; kk < 32; kk += 8) {
            unsigned a[4][4], b[8][2];
#pragma unroll
            for (int mi = 0; mi < 4; mi++) {
                int rr = wm + mi * 16;
                a[mi][0] = As[(rr + g)     * SMSTRIDE + kk + tg];
                a[mi][1] = As[(rr + g + 8) * SMSTRIDE + kk + tg];
                a[mi][2] = As[(rr + g)     * SMSTRIDE + kk + tg + 4];
                a[mi][3] = As[(rr + g + 8) * SMSTRIDE + kk + tg + 4];
            }
#pragma unroll
            for (int ni = 0; ni < 8; ni++) {
                int cc = wn + ni * 8 + g;
                b[ni][0] = Bs[cc * SMSTRIDE + kk + tg];
                b[ni][1] = Bs[cc * SMSTRIDE + kk + tg + 4];
            }
#pragma unroll
            for (int mi = 0; mi < 4; mi++)
#pragma unroll
                for (int ni = 0; ni < 8; ni++) {
                    asm volatile(
                        "mma.sync.aligned.m16n8k8.row.col.f32.tf32.tf32.f32 "
                        "{%0,%1,%2,%3}, {%4,%5,%6,%7}, {%8,%9}, {%0,%1,%2,%3};"
                        : "+f"(acc[mi][ni][0]), "+f"(acc[mi][ni][1]),
                          "+f"(acc[mi][ni][2]), "+f"(acc[mi][ni][3])
                        : "r"(a[mi][0]), "r"(a[mi][1]),
                          "r"(a[mi][2]), "r"(a[mi][3]),
                          "r"(b[ni][0]), "r"(b[ni][1]));
                }
        }
    }

#pragma unroll
    for (int mi = 0; mi < 4; mi++) {
        int row0 = (int)rowBase + wm + mi * 16 + g;
#pragma unroll
        for (int ni = 0; ni < 8; ni++) {
            int col = (int)colBase + wn + ni * 8 + 2 * tg;
            atomicAdd(&g_t1[row0 * H1 + col],           acc[mi][ni][0]);
            atomicAdd(&g_t1[row0 * H1 + col + 1],       acc[mi][ni][1]);
            atomicAdd(&g_t1[(row0 + 8) * H1 + col],     acc[mi][ni][2]);
            atomicAdd(&g_t1[(row0 + 8) * H1 + col + 1], acc[mi][ni][3]);
        }
    }
}

// ---------------------------------------------------------------------------
// K2 weff_k (72 blocks):
//   [0,64)  Weff = T1 @ W1 (fp32 FFMA 32x32 tiles, reg-prefetched) + round
//   [64,72) bn_final: 8 blocks x 32 cols, 8 threads per col, shfl reduce
// ---------------------------------------------------------------------------
__global__ __launch_bounds__(256)
void weff_k(const float* __restrict__ W1, const float* __restrict__ gamma,
            const float* __restrict__ beta) {
    int tid = threadIdx.x;
    if (blockIdx.x >= 64) {
        int c   = (blockIdx.x - 64) * 32 + (tid >> 3);
        int sub = tid & 7;
        float s = 0.f, q = 0.f;
#pragma unroll 8
        for (int b = sub; b < 256; b += 8) {
            s += g_partS[b * 256 + c];
            q += g_partQ[b * 256 + c];
        }
#pragma unroll
        for (int o = 4; o; o >>= 1) {
            s += __shfl_xor_sync(~0u, s, o);
            q += __shfl_xor_sync(~0u, q, o);
        }
        if (sub == 0) {
            const float inv = 1.0f / (float)NROWS;
            float mu  = s * inv;
            float var = q * inv - mu * mu;
            float sc  = gamma[c] * rsqrtf(var + 1e-5f);
            g_scale[c] = sc;
            g_shift[c] = beta[c] - mu * sc;
        }
        return;
    }
    __shared__ float As[32][36], Bs[32][36];
    int i0 = (blockIdx.x >> 3) * 32, j0 = (blockIdx.x & 7) * 32;
    int ty = tid >> 4, tx = tid & 15;
    int lr = tid >> 3, lc4 = (tid & 7) * 4;
    float a00 = 0.f, a01 = 0.f, a10 = 0.f, a11 = 0.f;

    float4 ra = *(const float4*)(&g_t1[(i0 + lr) * H1 + lc4]);
    float4 rb = *(const float4*)(&W1[(size_t)lr * DIM + j0 + lc4]);

    for (int kb = 0; kb < H1; kb += 32) {
        *(float4*)(&As[lr][lc4]) = ra;
        *(float4*)(&Bs[lr][lc4]) = rb;
        __syncthreads();
        if (kb + 32 < H1) {
            ra = *(const float4*)(&g_t1[(i0 + lr) * H1 + kb + 32 + lc4]);
            rb = *(const float4*)(&W1[(size_t)(kb + 32 + lr) * DIM + j0 + lc4]);
        }
#pragma unroll
        for (int k = 0; k < 32; k++) {
            float x0 = As[ty * 2][k],     x1 = As[ty * 2 + 1][k];
            float y0 = Bs[k][tx * 2],     y1 = Bs[k][tx * 2 + 1];
            a00 = fmaf(x0, y0, a00); a01 = fmaf(x0, y1, a01);
            a10 = fmaf(x1, y0, a10); a11 = fmaf(x1, y1, a11);
        }
        __syncthreads();
    }
    int r0 = i0 + ty * 2, c0 = j0 + tx * 2;
    g_weff[r0 * DIM + c0]           = __uint_as_float(f2tf(a00));
    g_weff[r0 * DIM + c0 + 1]       = __uint_as_float(f2tf(a01));
    g_weff[(r0 + 1) * DIM + c0]     = __uint_as_float(f2tf(a10));
    g_weff[(r0 + 1) * DIM + c0 + 1] = __uint_as_float(f2tf(a11));
}

// ---------------------------------------------------------------------------
// K3 fused final, 512 threads (16 warps, 4x4 warp grid of 32x64 tiles),
// chunk-pipelined: MMA(kt) overlaps x-load/tanh/pack of kt+1 + B cp of kt+2.
// ---------------------------------------------------------------------------
#define FA_STAGE 18432
#define FB_STAGE 36864
#define FA_TOTAL (8 * FA_STAGE)
#define F_SMEM   (FA_TOTAL + 2 * FB_STAGE)

__device__ __forceinline__ void issueB_f(uint32_t sbase, int slot, int kt, int tid) {
#pragma unroll
    for (int j = 0; j < 4; j++) {
        int r = (tid >> 3) + j * 64;
        cp16(sbase + FA_TOTAL + slot * FB_STAGE + r * ROWBYTES + (tid & 7) * 16,
             g_weff + r * 256 + kt * 32 + (tid & 7) * 4);
    }
}

__global__ __launch_bounds__(512, 1)
void fused_final(const float* __restrict__ x, float* __restrict__ raw,
                 float* __restrict__ out) {
    extern __shared__ char smem[];
    const uint32_t sbase = smem_u32(smem);
    const int tid  = threadIdx.x;
    const int lane = tid & 31;
    const int g    = lane >> 2;
    const int tg   = lane & 3;
    const int wid  = tid >> 5;            // 0..15
    const int wm   = (wid & 3) * 32;
    const int wn   = (wid >> 2) * 64;
    const size_t rowBase = (size_t)blockIdx.x * 128;

    issueB_f(sbase, 0, 0, tid);
    cp_commit();
    issueB_f(sbase, 1, 1, tid);
    cp_commit();

    const int cf = tid & 7;
    const float* xp[2];
    float* rp[2];
    uint32_t so[2];
#pragma unroll
    for (int j = 0; j < 2; j++) {
        int r = (tid >> 3) + j * 64;
        xp[j] = x   + (rowBase + r) * 256 + cf * 4;
        rp[j] = raw + (rowBase + r) * 256 + cf * 4;
        so[j] = r * ROWBYTES + cf * 16;
    }

    // generate chunk 0
    float4 nv[2];
#pragma unroll
    for (int j = 0; j < 2; j++) nv[j] = *(const float4*)(xp[j]);
    {
        float4 sc = ((const float4*)g_scale)[cf];
        float4 sh = ((const float4*)g_shift)[cf];
#pragma unroll
        for (int j = 0; j < 2; j++) {
            float4 xn;
            xn.x = fmaf(nv[j].x, sc.x, sh.x);
            xn.y = fmaf(nv[j].y, sc.y, sh.y);
            xn.z = fmaf(nv[j].z, sc.z, sh.z);
            xn.w = fmaf(nv[j].w, sc.w, sh.w);
            float4 t;
            t.x = tanh_ap(xn.x); t.y = tanh_ap(xn.y);
            t.z = tanh_ap(xn.z); t.w = tanh_ap(xn.w);
            *(float4*)(rp[j]) = t;
            uint4 rb;
            rb.x = f2tf(xn.x); rb.y = f2tf(xn.y);
            rb.z = f2tf(xn.z); rb.w = f2tf(xn.w);
            *(uint4*)(smem + so[j]) = rb;
        }
    }

    float acc[2][8][4];
#pragma unroll
    for (int mi = 0; mi < 2; mi++)
#pragma unroll
        for (int ni = 0; ni < 8; ni++)
#pragma unroll
            for (int k = 0; k < 4; k++) acc[mi][ni][k] = 0.f;

    for (int kt = 0; kt < 8; kt++) {
        if (kt < 7) {
#pragma unroll
            for (int j = 0; j < 2; j++)
                nv[j] = *(const float4*)(xp[j] + (kt + 1) * 32);
        }
        cp_wait<1>();
        __syncthreads();

        const unsigned* As = (const unsigned*)(smem + kt * FA_STAGE);
        const unsigned* Bs = (const unsigned*)(smem + FA_TOTAL + (kt & 1) * FB_STAGE);
#pragma unroll
        for (int kk = 0; kk < 32; kk += 8) {
            unsigned a[2][4], b[8][2];
#pragma unroll
            for (int mi = 0; mi < 2; mi++) {
                int rr = wm + mi * 16;
                a[mi][0] = As[(rr + g)     * SMSTRIDE + kk + tg];
                a[mi][1] = As[(rr + g + 8) * SMSTRIDE + kk + tg];
                a[mi][2] = As[(rr + g)     * SMSTRIDE + kk + tg + 4];
                a[mi][3] = As[(rr + g + 8) * SMSTRIDE + kk + tg + 4];
            }
#pragma unroll
            for (int ni = 0; ni < 8; ni++) {
                int cc = wn + ni * 8 + g;
                b[ni][0] = Bs[cc * SMSTRIDE + kk + tg];
                b[ni][1] = Bs[cc * SMSTRIDE + kk + tg + 4];
            }
#pragma unroll
            for (int mi = 0; mi < 2; mi++)
#pragma unroll
                for (int ni = 0; ni < 8; ni++) {
                    asm volatile(
                        "mma.sync.aligned.m16n8k8.row.col.f32.tf32.tf32.f32 "
                        "{%0,%1,%2,%3}, {%4,%5,%6,%7}, {%8,%9}, {%0,%1,%2,%3};"
                        : "+f"(acc[mi][ni][0]), "+f"(acc[mi][ni][1]),
                          "+f"(acc[mi][ni][2]), "+f"(acc[mi][ni][3])
                        : "r"(a[mi][0]), "r"(a[mi][1]),
                          "r"(a[mi][2]), "r"(a[mi][3]),
                          "r"(b[ni][0]), "r"(b[ni][1]));
                }
        }

        if (kt < 7) {
            float4 sc = ((const float4*)g_scale)[(kt + 1) * 8 + cf];
            float4 sh = ((const float4*)g_shift)[(kt + 1) * 8 + cf];
#pragma unroll
            for (int j = 0; j < 2; j++) {
                float4 xn;
                xn.x = fmaf(nv[j].x, sc.x, sh.x);
                xn.y = fmaf(nv[j].y, sc.y, sh.y);
                xn.z = fmaf(nv[j].z, sc.z, sh.z);
                xn.w = fmaf(nv[j].w, sc.w, sh.w);
                float4 t;
                t.x = tanh_ap(xn.x); t.y = tanh_ap(xn.y);
                t.z = tanh_ap(xn.z); t.w = tanh_ap(xn.w);
                *(float4*)(rp[j] + (kt + 1) * 32) = t;
                uint4 rb;
                rb.x = f2tf(xn.x); rb.y = f2tf(xn.y);
                rb.z = f2tf(xn.z); rb.w = f2tf(xn.w);
                *(uint4*)(smem + so[j] + (kt + 1) * FA_STAGE) = rb;
            }
        }
        __syncthreads();
        if (kt + 2 < 8) issueB_f(sbase, kt & 1, kt + 2, tid);
        cp_commit();
    }

#pragma unroll
    for (int mi = 0; mi < 2; mi++) {
        size_t row0 = rowBase + wm + mi * 16 + g;
#pragma unroll
        for (int ni = 0; ni < 8; ni++) {
            int col = wn + ni * 8 + 2 * tg;
            float v0 = tanh_ap(acc[mi][ni][0] + g_beff[col]);
            float v1 = tanh_ap(acc[mi][ni][1] + g_beff[col + 1]);
            float v2 = tanh_ap(acc[mi][ni][2] + g_beff[col]);
            float v3 = tanh_ap(acc[mi][ni][3] + g_beff[col + 1]);
            *(float2*)&out[row0 * 256 + col]       = make_float2(v0, v1);
            *(float2*)&out[(row0 + 8) * 256 + col] = make_float2(v2, v3);
        }
    }
}

// ---------------------------------------------------------------------------
// Launch (4 kernels)
// ---------------------------------------------------------------------------
extern "C" void kernel_launch(void* const* d_in, const int* in_sizes, int n_in,
                              void* d_out, int out_size) {
    const float* x     = (const float*)d_in[0];
    const float* gamma = (const float*)d_in[1];
    const float* beta  = (const float*)d_in[2];
    const float* W1    = (const float*)d_in[3];
    const float* b1    = (const float*)d_in[4];
    const float* W2    = (const float*)d_in[5];
    const float* b2    = (const float*)d_in[6];
    const float* Wf    = (const float*)d_in[7];
    const float* bf    = (const float*)d_in[8];

    float* out = (float*)d_out;
    float* raw = out + (size_t)NROWS * DIM;

    cudaFuncSetAttribute(wchain,
                         cudaFuncAttributeMaxDynamicSharedMemorySize, GEMM_SMEM);
    cudaFuncSetAttribute(fused_final,
                         cudaFuncAttributeMaxDynamicSharedMemorySize, F_SMEM);

    prep<<<552, 256>>>(W2, Wf, b1, b2);
    wchain<<<320, 256, GEMM_SMEM>>>(x, Wf, bf);
    weff_k<<<72, 256>>>(W1, gamma, beta);
    fused_final<<<NROWS / 128, 512, F_SMEM>>>(x, raw, out);
}

// round 9
// speedup vs baseline: 12.7606x; 1.0453x over previous
#include <cuda_runtime.h>
#include <math.h>
#include <cstdint>

#define NROWS 65536
#define DIM   256
#define H1    512
#define H2    2048

// ---------------------------------------------------------------------------
// Device scratch (allocation-free rule)
// ---------------------------------------------------------------------------
__device__ __align__(16) float g_partS[256 * 256];
__device__ __align__(16) float g_partQ[256 * 256];
__device__ __align__(16) float g_scale[DIM];
__device__ __align__(16) float g_shift[DIM];
__device__ __align__(16) float g_w2t[H1 * H2];        // W2^T rounded [512,2048]
__device__ __align__(16) float g_wfr[DIM * H2];       // Wf rounded   [256,2048]
__device__ __align__(16) float g_t2[H2];              // W2@b1 + b2
__device__ __align__(16) float g_beff[DIM];           // Wf@t2 + bf
__device__ __align__(16) float g_t1[DIM * H1];        // T1 = Wf@W2 fp32 (atomic acc)
__device__ __align__(16) float g_weff[DIM * DIM];     // Wf@W2@W1 rounded [256,256]

// ---------------------------------------------------------------------------
// Helpers
// ---------------------------------------------------------------------------
__device__ __forceinline__ unsigned f2tf(float f) {
    unsigned u;
    asm("cvt.rna.tf32.f32 %0, %1;" : "=r"(u) : "f"(f));
    return u;
}
__device__ __forceinline__ float tanh_ap(float x) {
    float r;
    asm("tanh.approx.f32 %0, %1;" : "=f"(r) : "f"(x));
    return r;
}
__device__ __forceinline__ uint32_t smem_u32(const void* p) {
    uint32_t a;
    asm("{ .reg .u64 t; cvta.to.shared.u64 t, %1; cvt.u32.u64 %0, t; }"
        : "=r"(a) : "l"(p));
    return a;
}
__device__ __forceinline__ void cp16(uint32_t dst, const void* src) {
    asm volatile("cp.async.cg.shared.global [%0], [%1], 16;"
                 :: "r"(dst), "l"(src));
}
__device__ __forceinline__ void cp_commit() {
    asm volatile("cp.async.commit_group;" ::: "memory");
}
template <int N>
__device__ __forceinline__ void cp_wait() {
    asm volatile("cp.async.wait_group %0;" :: "n"(N) : "memory");
}

// ---------------------------------------------------------------------------
// K0 prep (808 blocks):
//   [0,256)   bn x-scan (float4, 256 rows per block, smem reduce)
//   [256,512) W2 transpose + tf32 round -> g_w2t
//   [512,544) round Wf -> g_wfr
//   [544,800) t2 = W2@b1 + b2
//   [800,808) zero g_t1
// ---------------------------------------------------------------------------
__global__ __launch_bounds__(256)
void prep(const float* __restrict__ x, const float* __restrict__ W2,
          const float* __restrict__ Wf, const float* __restrict__ b1,
          const float* __restrict__ b2) {
    __shared__ float ts[64][65];
    int bx = blockIdx.x, tid = threadIdx.x;
    if (bx < 256) {
        __shared__ float4 rs[4][64], rq[4][64];
        int rg = tid >> 6;                 // 0..3 row groups
        int tc = tid & 63;                 // float4 column
        const float4* xp = (const float4*)(x + (size_t)(bx * 256 + rg * 64) * DIM) + tc;
        float4 s = make_float4(0.f, 0.f, 0.f, 0.f);
        float4 q = make_float4(0.f, 0.f, 0.f, 0.f);
#pragma unroll 8
        for (int i = 0; i < 64; i++) {
            float4 v = xp[(size_t)i * 64];
            s.x += v.x; s.y += v.y; s.z += v.z; s.w += v.w;
            q.x += v.x * v.x; q.y += v.y * v.y;
            q.z += v.z * v.z; q.w += v.w * v.w;
        }
        rs[rg][tc] = s; rq[rg][tc] = q;
        __syncthreads();
        if (rg == 0) {
#pragma unroll
            for (int z = 1; z < 4; z++) {
                float4 a = rs[z][tc], b = rq[z][tc];
                s.x += a.x; s.y += a.y; s.z += a.z; s.w += a.w;
                q.x += b.x; q.y += b.y; q.z += b.z; q.w += b.w;
            }
            ((float4*)(g_partS + bx * 256))[tc] = s;
            ((float4*)(g_partQ + bx * 256))[tc] = q;
        }
    } else if (bx < 512) {
        int b2i = bx - 256;
        int i0 = (b2i & 31) * 64;          // over 2048
        int j0 = (b2i >> 5) * 64;          // over 512
#pragma unroll
        for (int t = 0; t < 16; t++) {
            int e = tid + t * 256;
            int r = e >> 6, c = e & 63;
            ts[r][c] = W2[(size_t)(i0 + r) * H1 + j0 + c];
        }
        __syncthreads();
#pragma unroll
        for (int t = 0; t < 16; t++) {
            int e = tid + t * 256;
            int r = e >> 6, c = e & 63;
            g_w2t[(size_t)(j0 + r) * H2 + i0 + c] =
                __uint_as_float(f2tf(ts[c][r]));
        }
    } else if (bx < 544) {
        int base = (bx - 512) * 4096;
#pragma unroll
        for (int t = 0; t < 16; t++) {
            int i = base + tid + t * 256;
            float4 v = ((const float4*)Wf)[i];
            v.x = __uint_as_float(f2tf(v.x));
            v.y = __uint_as_float(f2tf(v.y));
            v.z = __uint_as_float(f2tf(v.z));
            v.w = __uint_as_float(f2tf(v.w));
            ((float4*)g_wfr)[i] = v;
        }
    } else if (bx < 800) {
        int w = tid >> 5, lane = tid & 31;
        int row = (bx - 544) * 8 + w;
        const float* wr = W2 + (size_t)row * H1;
        float s = 0.f;
#pragma unroll
        for (int i = 0; i < H1 / 32; i++)
            s += wr[lane + i * 32] * b1[lane + i * 32];
#pragma unroll
        for (int o = 16; o; o >>= 1) s += __shfl_xor_sync(~0u, s, o);
        if (lane == 0) g_t2[row] = s + b2[row];
    } else {
        int base = (bx - 800) * 4096;
        float4 z = make_float4(0.f, 0.f, 0.f, 0.f);
#pragma unroll
        for (int t = 0; t < 16; t++)
            ((float4*)g_t1)[base + tid + t * 256] = z;
    }
}

// ---------------------------------------------------------------------------
// K1 wchain (96 blocks, GEMM_SMEM dyn smem):
//   [0,64)  split-K(16) tf32 GEMM: T1 += Wf @ W2^T  (atomicAdd epilogue)
//   [64,96) beff = Wf@t2 + bf
// ---------------------------------------------------------------------------
#define SMSTRIDE   36
#define ROWBYTES   (SMSTRIDE * 4)
#define A_BYTES    (128 * ROWBYTES)
#define B_BYTES    (256 * ROWBYTES)
#define STAGE_B    (A_BYTES + B_BYTES)
#define STAGES     3
#define GEMM_SMEM  (STAGES * STAGE_B)

__device__ __forceinline__ void issue_tile(const float* aPtr, const float* bPtr,
                                           uint32_t sA, uint32_t sB,
                                           int kOff, int K) {
#pragma unroll
    for (int j = 0; j < 4; j++)
        cp16(sA + j * 32 * ROWBYTES, aPtr + (size_t)j * 32 * K + kOff);
#pragma unroll
    for (int j = 0; j < 8; j++)
        cp16(sB + j * 32 * ROWBYTES, bPtr + (size_t)j * 32 * K + kOff);
}

__global__ __launch_bounds__(256, 1)
void wchain(const float* __restrict__ Wf, const float* __restrict__ bf) {
    extern __shared__ char smem[];
    const int bx = blockIdx.x;
    const int tid = threadIdx.x;

    if (bx >= 64) {               // ---- beff ----
        int w = tid >> 5, lane = tid & 31;
        int row = (bx - 64) * 8 + w;
        const float* wr = Wf + (size_t)row * H2;
        float s = 0.f;
#pragma unroll
        for (int i = 0; i < H2 / 32; i++)
            s += wr[lane + i * 32] * g_t2[lane + i * 32];
#pragma unroll
        for (int o = 16; o; o >>= 1) s += __shfl_xor_sync(~0u, s, o);
        if (lane == 0) g_beff[row] = s + bf[row];
        return;
    }

    // ---- split-K(16) GEMM: A=g_wfr [256,2048], W=g_w2t [512,2048], slice 128 ----
    const uint32_t sbase = smem_u32(smem);
    const int lane = tid & 31;
    const int g    = lane >> 2;
    const int tg   = lane & 3;
    const int wid  = tid >> 5;
    const int wm   = (wid & 1) * 64;
    const int wn   = (wid >> 1) * 64;

    const int xx = bx & 1, yy = (bx >> 1) & 1, z = bx >> 2;   // z: 0..15
    const int K = H2, kloop = 128, T = kloop >> 5;            // T = 4
    const float* A = g_wfr + z * kloop;
    const float* W = g_w2t + z * kloop;

    const size_t rowBase = (size_t)yy * 128;
    const size_t colBase = (size_t)xx * 256;

    const int r0 = tid >> 3;
    const int c0 = tid & 7;
    const float* aPtr = A + (rowBase + r0) * (size_t)K + c0 * 4;
    const float* bPtr = W + (colBase + r0) * (size_t)K + c0 * 4;
    const uint32_t sAo = r0 * ROWBYTES + c0 * 16;
    const uint32_t sBo = A_BYTES + r0 * ROWBYTES + c0 * 16;

    float acc[4][8][4];
#pragma unroll
    for (int mi = 0; mi < 4; mi++)
#pragma unroll
        for (int ni = 0; ni < 8; ni++)
#pragma unroll
            for (int k = 0; k < 4; k++) acc[mi][ni][k] = 0.f;

    issue_tile(aPtr, bPtr, sbase + sAo, sbase + sBo, 0, K);
    cp_commit();
    issue_tile(aPtr, bPtr, sbase + STAGE_B + sAo, sbase + STAGE_B + sBo, 32, K);
    cp_commit();

    for (int kt = 0; kt < T; kt++) {
        cp_wait<1>();
        __syncthreads();
        if (kt + 2 < T) {
            uint32_t sb2 = sbase + ((kt + 2) % STAGES) * STAGE_B;
            issue_tile(aPtr, bPtr, sb2 + sAo, sb2 + sBo, (kt + 2) * 32, K);
        }
        cp_commit();

        const unsigned* As = (const unsigned*)(smem + (kt % STAGES) * STAGE_B);
        const unsigned* Bs = (const unsigned*)(smem + (kt % STAGES) * STAGE_B + A_BYTES);
#pragma unroll
        for (int kk = 0; kk < 32; kk += 8) {
            unsigned a[4][4], b[8][2];
#pragma unroll
            for (int mi = 0; mi < 4; mi++) {
                int rr = wm + mi * 16;
                a[mi][0] = As[(rr + g)     * SMSTRIDE + kk + tg];
                a[mi][1] = As[(rr + g + 8) * SMSTRIDE + kk + tg];
                a[mi][2] = As[(rr + g)     * SMSTRIDE + kk + tg + 4];
                a[mi][3] = As[(rr + g + 8) * SMSTRIDE + kk + tg + 4];
            }
#pragma unroll
            for (int ni = 0; ni < 8; ni++) {
                int cc = wn + ni * 8 + g;
                b[ni][0] = Bs[cc * SMSTRIDE + kk + tg];
                b[ni][1] = Bs[cc * SMSTRIDE + kk + tg + 4];
            }
#pragma unroll
            for (int mi = 0; mi < 4; mi++)
#pragma unroll
                for (int ni = 0; ni < 8; ni++) {
                    asm volatile(
                        "mma.sync.aligned.m16n8k8.row.col.f32.tf32.tf32.f32 "
                        "{%0,%1,%2,%3}, {%4,%5,%6,%7}, {%8,%9}, {%0,%1,%2,%3};"
                        : "+f"(acc[mi][ni][0]), "+f"(acc[mi][ni][1]),
                          "+f"(acc[mi][ni][2]), "+f"(acc[mi][ni][3])
                        : "r"(a[mi][0]), "r"(a[mi][1]),
                          "r"(a[mi][2]), "r"(a[mi][3]),
                          "r"(b[ni][0]), "r"(b[ni][1]));
                }
        }
    }

#pragma unroll
    for (int mi = 0; mi < 4; mi++) {
        int row0 = (int)rowBase + wm + mi * 16 + g;
#pragma unroll
        for (int ni = 0; ni < 8; ni++) {
            int col = (int)colBase + wn + ni * 8 + 2 * tg;
            atomicAdd(&g_t1[row0 * H1 + col],           acc[mi][ni][0]);
            atomicAdd(&g_t1[row0 * H1 + col + 1],       acc[mi][ni][1]);
            atomicAdd(&g_t1[(row0 + 8) * H1 + col],     acc[mi][ni][2]);
            atomicAdd(&g_t1[(row0 + 8) * H1 + col + 1], acc[mi][ni][3]);
        }
    }
}

// ---------------------------------------------------------------------------
// K2 weff_k (72 blocks):
//   [0,64)  Weff = T1 @ W1 (fp32 FFMA 32x32 tiles, reg-prefetched) + round
//   [64,72) bn_final
// ---------------------------------------------------------------------------
__global__ __launch_bounds__(256)
void weff_k(const float* __restrict__ W1, const float* __restrict__ gamma,
            const float* __restrict__ beta) {
    int tid = threadIdx.x;
    if (blockIdx.x >= 64) {
        int c   = (blockIdx.x - 64) * 32 + (tid >> 3);
        int sub = tid & 7;
        float s = 0.f, q = 0.f;
#pragma unroll 8
        for (int b = sub; b < 256; b += 8) {
            s += g_partS[b * 256 + c];
            q += g_partQ[b * 256 + c];
        }
#pragma unroll
        for (int o = 4; o; o >>= 1) {
            s += __shfl_xor_sync(~0u, s, o);
            q += __shfl_xor_sync(~0u, q, o);
        }
        if (sub == 0) {
            const float inv = 1.0f / (float)NROWS;
            float mu  = s * inv;
            float var = q * inv - mu * mu;
            float sc  = gamma[c] * rsqrtf(var + 1e-5f);
            g_scale[c] = sc;
            g_shift[c] = beta[c] - mu * sc;
        }
        return;
    }
    __shared__ float As[32][36], Bs[32][36];
    int i0 = (blockIdx.x >> 3) * 32, j0 = (blockIdx.x & 7) * 32;
    int ty = tid >> 4, tx = tid & 15;
    int lr = tid >> 3, lc4 = (tid & 7) * 4;
    float a00 = 0.f, a01 = 0.f, a10 = 0.f, a11 = 0.f;

    float4 ra = *(const float4*)(&g_t1[(i0 + lr) * H1 + lc4]);
    float4 rb = *(const float4*)(&W1[(size_t)lr * DIM + j0 + lc4]);

    for (int kb = 0; kb < H1; kb += 32) {
        *(float4*)(&As[lr][lc4]) = ra;
        *(float4*)(&Bs[lr][lc4]) = rb;
        __syncthreads();
        if (kb + 32 < H1) {
            ra = *(const float4*)(&g_t1[(i0 + lr) * H1 + kb + 32 + lc4]);
            rb = *(const float4*)(&W1[(size_t)(kb + 32 + lr) * DIM + j0 + lc4]);
        }
#pragma unroll
        for (int k = 0; k < 32; k++) {
            float x0 = As[ty * 2][k],     x1 = As[ty * 2 + 1][k];
            float y0 = Bs[k][tx * 2],     y1 = Bs[k][tx * 2 + 1];
            a00 = fmaf(x0, y0, a00); a01 = fmaf(x0, y1, a01);
            a10 = fmaf(x1, y0, a10); a11 = fmaf(x1, y1, a11);
        }
        __syncthreads();
    }
    int r0 = i0 + ty * 2, c0 = j0 + tx * 2;
    g_weff[r0 * DIM + c0]           = __uint_as_float(f2tf(a00));
    g_weff[r0 * DIM + c0 + 1]       = __uint_as_float(f2tf(a01));
    g_weff[(r0 + 1) * DIM + c0]     = __uint_as_float(f2tf(a10));
    g_weff[(r0 + 1) * DIM + c0 + 1] = __uint_as_float(f2tf(a11));
}

// ---------------------------------------------------------------------------
// K3 fused final: 128x128 CTA tile, 256 threads, 2 CTAs/SM.
// A double-buffered (generated in-kernel), B double-buffered (cp.async).
// grid (2, 512): blockIdx.x = column half; col-half 0 also writes raw.
// smem: A[2][18432] | B[2][18432] = 73728 B.
// ---------------------------------------------------------------------------
#define FA_STAGE 18432
#define FB_OFF   (2 * FA_STAGE)
#define F_SMEM   (4 * FA_STAGE)        // 73728

__device__ __forceinline__ void issueB_f(uint32_t sbase, int slot, int kt,
                                         int tid, int colBase) {
#pragma unroll
    for (int j = 0; j < 4; j++) {
        int r = (tid >> 3) + j * 32;
        cp16(sbase + FB_OFF + slot * FA_STAGE + r * ROWBYTES + (tid & 7) * 16,
             g_weff + (colBase + r) * 256 + kt * 32 + (tid & 7) * 4);
    }
}

__global__ __launch_bounds__(256, 2)
void fused_final(const float* __restrict__ x, float* __restrict__ raw,
                 float* __restrict__ out) {
    extern __shared__ char smem[];
    const uint32_t sbase = smem_u32(smem);
    const int tid  = threadIdx.x;
    const int lane = tid & 31;
    const int g    = lane >> 2;
    const int tg   = lane & 3;
    const int wid  = tid >> 5;            // 0..7
    const int wm   = (wid & 3) * 32;      // 4 M-warps
    const int wn   = (wid >> 2) * 64;     // 2 N-warps
    const int colBase = blockIdx.x * 128;
    const bool doRaw  = (blockIdx.x == 0);
    const size_t rowBase = (size_t)blockIdx.y * 128;

    issueB_f(sbase, 0, 0, tid, colBase);
    cp_commit();
    issueB_f(sbase, 1, 1, tid, colBase);
    cp_commit();

    // A-gen geometry: thread covers 4 rows (j), fixed float4 column cf
    const int cf = tid & 7;
    const float* xp[4];
    float* rp[4];
    uint32_t so[4];
#pragma unroll
    for (int j = 0; j < 4; j++) {
        int r = (tid >> 3) + j * 32;
        xp[j] = x   + (rowBase + r) * 256 + cf * 4;
        rp[j] = raw + (rowBase + r) * 256 + cf * 4;
        so[j] = r * ROWBYTES + cf * 16;
    }

    // generate chunk 0 into A slot 0
    float4 nv[4];
#pragma unroll
    for (int j = 0; j < 4; j++) nv[j] = *(const float4*)(xp[j]);
    {
        float4 sc = ((const float4*)g_scale)[cf];
        float4 sh = ((const float4*)g_shift)[cf];
#pragma unroll
        for (int j = 0; j < 4; j++) {
            float4 xn;
            xn.x = fmaf(nv[j].x, sc.x, sh.x);
            xn.y = fmaf(nv[j].y, sc.y, sh.y);
            xn.z = fmaf(nv[j].z, sc.z, sh.z);
            xn.w = fmaf(nv[j].w, sc.w, sh.w);
            if (doRaw) {
                float4 t;
                t.x = tanh_ap(xn.x); t.y = tanh_ap(xn.y);
                t.z = tanh_ap(xn.z); t.w = tanh_ap(xn.w);
                *(float4*)(rp[j]) = t;
            }
            uint4 rb;
            rb.x = f2tf(xn.x); rb.y = f2tf(xn.y);
            rb.z = f2tf(xn.z); rb.w = f2tf(xn.w);
            *(uint4*)(smem + so[j]) = rb;
        }
    }

    float acc[2][8][4];
#pragma unroll
    for (int mi = 0; mi < 2; mi++)
#pragma unroll
        for (int ni = 0; ni < 8; ni++)
#pragma unroll
            for (int k = 0; k < 4; k++) acc[mi][ni][k] = 0.f;

    for (int kt = 0; kt < 8; kt++) {
        if (kt < 7) {
#pragma unroll
            for (int j = 0; j < 4; j++)
                nv[j] = *(const float4*)(xp[j] + (kt + 1) * 32);
        }
        cp_wait<1>();
        __syncthreads();

        const unsigned* As = (const unsigned*)(smem + (kt & 1) * FA_STAGE);
        const unsigned* Bs = (const unsigned*)(smem + FB_OFF + (kt & 1) * FA_STAGE);
#pragma unroll
        for (int kk = 0; kk < 32; kk += 8) {
            unsigned a[2][4], b[8][2];
#pragma unroll
            for (int mi = 0; mi < 2; mi++) {
                int rr = wm + mi * 16;
                a[mi][0] = As[(rr + g)     * SMSTRIDE + kk + tg];
                a[mi][1] = As[(rr + g + 8) * SMSTRIDE + kk + tg];
                a[mi][2] = As[(rr + g)     * SMSTRIDE + kk + tg + 4];
                a[mi][3] = As[(rr + g + 8) * SMSTRIDE + kk + tg + 4];
            }
#pragma unroll
            for (int ni = 0; ni < 8; ni++) {
                int cc = wn + ni * 8 + g;
                b[ni][0] = Bs[cc * SMSTRIDE + kk + tg];
                b[ni][1] = Bs[cc * SMSTRIDE + kk + tg + 4];
            }
#pragma unroll
            for (int mi = 0; mi < 2; mi++)
#pragma unroll
                for (int ni = 0; ni < 8; ni++) {
                    asm volatile(
                        "mma.sync.aligned.m16n8k8.row.col.f32.tf32.tf32.f32 "
                        "{%0,%1,%2,%3}, {%4,%5,%6,%7}, {%8,%9}, {%0,%1,%2,%3};"
                        : "+f"(acc[mi][ni][0]), "+f"(acc[mi][ni][1]),
                          "+f"(acc[mi][ni][2]), "+f"(acc[mi][ni][3])
                        : "r"(a[mi][0]), "r"(a[mi][1]),
                          "r"(a[mi][2]), "r"(a[mi][3]),
                          "r"(b[ni][0]), "r"(b[ni][1]));
                }
        }

        // generate chunk kt+1 into A slot (kt+1)&1 (safe: all warps passed
        // MMA(kt-1) at the barrier above, which last read that slot)
        if (kt < 7) {
            float4 sc = ((const float4*)g_scale)[(kt + 1) * 8 + cf];
            float4 sh = ((const float4*)g_shift)[(kt + 1) * 8 + cf];
#pragma unroll
            for (int j = 0; j < 4; j++) {
                float4 xn;
                xn.x = fmaf(nv[j].x, sc.x, sh.x);
                xn.y = fmaf(nv[j].y, sc.y, sh.y);
                xn.z = fmaf(nv[j].z, sc.z, sh.z);
                xn.w = fmaf(nv[j].w, sc.w, sh.w);
                if (doRaw) {
                    float4 t;
                    t.x = tanh_ap(xn.x); t.y = tanh_ap(xn.y);
                    t.z = tanh_ap(xn.z); t.w = tanh_ap(xn.w);
                    *(float4*)(rp[j] + (kt + 1) * 32) = t;
                }
                uint4 rb;
                rb.x = f2tf(xn.x); rb.y = f2tf(xn.y);
                rb.z = f2tf(xn.z); rb.w = f2tf(xn.w);
                *(uint4*)(smem + ((kt + 1) & 1) * FA_STAGE + so[j]) = rb;
            }
        }
        __syncthreads();               // all warps done reading B slot kt&1
        if (kt + 2 < 8) issueB_f(sbase, kt & 1, kt + 2, tid, colBase);
        cp_commit();
    }

    // epilogue: + beff, tanh, store
#pragma unroll
    for (int mi = 0; mi < 2; mi++) {
        size_t row0 = rowBase + wm + mi * 16 + g;
#pragma unroll
        for (int ni = 0; ni < 8; ni++) {
            int col = colBase + wn + ni * 8 + 2 * tg;
            float v0 = tanh_ap(acc[mi][ni][0] + g_beff[col]);
            float v1 = tanh_ap(acc[mi][ni][1] + g_beff[col + 1]);
            float v2 = tanh_ap(acc[mi][ni][2] + g_beff[col]);
            float v3 = tanh_ap(acc[mi][ni][3] + g_beff[col + 1]);
            *(float2*)&out[row0 * 256 + col]       = make_float2(v0, v1);
            *(float2*)&out[(row0 + 8) * 256 + col] = make_float2(v2, v3);
        }
    }
}

// ---------------------------------------------------------------------------
// Launch (4 kernels)
// ---------------------------------------------------------------------------
extern "C" void kernel_launch(void* const* d_in, const int* in_sizes, int n_in,
                              void* d_out, int out_size) {
    const float* x     = (const float*)d_in[0];
    const float* gamma = (const float*)d_in[1];
    const float* beta  = (const float*)d_in[2];
    const float* W1    = (const float*)d_in[3];
    const float* b1    = (const float*)d_in[4];
    const float* W2    = (const float*)d_in[5];
    const float* b2    = (const float*)d_in[6];
    const float* Wf    = (const float*)d_in[7];
    const float* bf    = (const float*)d_in[8];

    float* out = (float*)d_out;
    float* raw = out + (size_t)NROWS * DIM;

    cudaFuncSetAttribute(wchain,
                         cudaFuncAttributeMaxDynamicSharedMemorySize, GEMM_SMEM);
    cudaFuncSetAttribute(fused_final,
                         cudaFuncAttributeMaxDynamicSharedMemorySize, F_SMEM);

    prep<<<808, 256>>>(x, W2, Wf, b1, b2);
    wchain<<<96, 256, GEMM_SMEM>>>(Wf, bf);
    weff_k<<<72, 256>>>(W1, gamma, beta);
    fused_final<<<dim3(2, NROWS / 128), 256, F_SMEM>>>(x, raw, out);
}

// round 10
// speedup vs baseline: 13.0317x; 1.0212x over previous
#include <cuda_runtime.h>
#include <math.h>
#include <cstdint>

#define NROWS 65536
#define DIM   256
#define H1    512
#define H2    2048

// ---------------------------------------------------------------------------
// Device scratch (allocation-free rule)
// ---------------------------------------------------------------------------
__device__ __align__(16) float g_partS[256 * 256];
__device__ __align__(16) float g_partQ[256 * 256];
__device__ __align__(16) float g_scale[DIM];
__device__ __align__(16) float g_shift[DIM];
__device__ __align__(16) float g_w2t[H1 * H2];        // W2^T rounded [512,2048]
__device__ __align__(16) float g_wfr[DIM * H2];       // Wf rounded   [256,2048]
__device__ __align__(16) float g_t2[H2];              // W2@b1 + b2
__device__ __align__(16) float g_beff[DIM];           // Wf@t2 + bf
__device__ __align__(16) float g_t1[DIM * H1];        // T1 = Wf@W2 fp32 (atomic acc)
__device__ __align__(16) float g_weff[DIM * DIM];     // Wf@W2@W1 rounded [256,256]

// ---------------------------------------------------------------------------
// Helpers
// ---------------------------------------------------------------------------
__device__ __forceinline__ unsigned f2tf(float f) {
    unsigned u;
    asm("cvt.rna.tf32.f32 %0, %1;" : "=r"(u) : "f"(f));
    return u;
}
__device__ __forceinline__ float tanh_ap(float x) {
    float r;
    asm("tanh.approx.f32 %0, %1;" : "=f"(r) : "f"(x));
    return r;
}
__device__ __forceinline__ uint32_t smem_u32(const void* p) {
    uint32_t a;
    asm("{ .reg .u64 t; cvta.to.shared.u64 t, %1; cvt.u32.u64 %0, t; }"
        : "=r"(a) : "l"(p));
    return a;
}
__device__ __forceinline__ void cp16(uint32_t dst, const void* src) {
    asm volatile("cp.async.cg.shared.global [%0], [%1], 16;"
                 :: "r"(dst), "l"(src));
}
__device__ __forceinline__ void cp_commit() {
    asm volatile("cp.async.commit_group;" ::: "memory");
}
template <int N>
__device__ __forceinline__ void cp_wait() {
    asm volatile("cp.async.wait_group %0;" :: "n"(N) : "memory");
}

// x-scan helper: one block reduces 256 rows starting at rowBase into partial id
__device__ __forceinline__ void xscan_block(const float* __restrict__ x,
                                            int part_id, int row0, int tid) {
    __shared__ float4 rs[4][64], rq[4][64];
    int rg = tid >> 6;                 // 0..3 row groups
    int tc = tid & 63;                 // float4 column
    const float4* xp = (const float4*)(x + (size_t)(row0 + rg * 64) * DIM) + tc;
    float4 s = make_float4(0.f, 0.f, 0.f, 0.f);
    float4 q = make_float4(0.f, 0.f, 0.f, 0.f);
#pragma unroll 8
    for (int i = 0; i < 64; i++) {
        float4 v = xp[(size_t)i * 64];
        s.x += v.x; s.y += v.y; s.z += v.z; s.w += v.w;
        q.x += v.x * v.x; q.y += v.y * v.y;
        q.z += v.z * v.z; q.w += v.w * v.w;
    }
    rs[rg][tc] = s; rq[rg][tc] = q;
    __syncthreads();
    if (rg == 0) {
#pragma unroll
        for (int z = 1; z < 4; z++) {
            float4 a = rs[z][tc], b = rq[z][tc];
            s.x += a.x; s.y += a.y; s.z += a.z; s.w += a.w;
            q.x += b.x; q.y += b.y; q.z += b.z; q.w += b.w;
        }
        ((float4*)(g_partS + part_id * 256))[tc] = s;
        ((float4*)(g_partQ + part_id * 256))[tc] = q;
    }
}

// ---------------------------------------------------------------------------
// K0 prep (680 blocks):
//   [0,128)   bn x-scan first half (rows 0..32767)
//   [128,384) W2 transpose + tf32 round -> g_w2t
//   [384,416) round Wf -> g_wfr
//   [416,672) t2 = W2@b1 + b2
//   [672,680) zero g_t1
// ---------------------------------------------------------------------------
__global__ __launch_bounds__(256)
void prep(const float* __restrict__ x, const float* __restrict__ W2,
          const float* __restrict__ Wf, const float* __restrict__ b1,
          const float* __restrict__ b2) {
    __shared__ float ts[64][65];
    int bx = blockIdx.x, tid = threadIdx.x;
    if (bx < 128) {
        xscan_block(x, bx, bx * 256, tid);
    } else if (bx < 384) {
        int b2i = bx - 128;
        int i0 = (b2i & 31) * 64;          // over 2048
        int j0 = (b2i >> 5) * 64;          // over 512
#pragma unroll
        for (int t = 0; t < 16; t++) {
            int e = tid + t * 256;
            int r = e >> 6, c = e & 63;
            ts[r][c] = W2[(size_t)(i0 + r) * H1 + j0 + c];
        }
        __syncthreads();
#pragma unroll
        for (int t = 0; t < 16; t++) {
            int e = tid + t * 256;
            int r = e >> 6, c = e & 63;
            g_w2t[(size_t)(j0 + r) * H2 + i0 + c] =
                __uint_as_float(f2tf(ts[c][r]));
        }
    } else if (bx < 416) {
        int base = (bx - 384) * 4096;
#pragma unroll
        for (int t = 0; t < 16; t++) {
            int i = base + tid + t * 256;
            float4 v = ((const float4*)Wf)[i];
            v.x = __uint_as_float(f2tf(v.x));
            v.y = __uint_as_float(f2tf(v.y));
            v.z = __uint_as_float(f2tf(v.z));
            v.w = __uint_as_float(f2tf(v.w));
            ((float4*)g_wfr)[i] = v;
        }
    } else if (bx < 672) {
        int w = tid >> 5, lane = tid & 31;
        int row = (bx - 416) * 8 + w;
        const float* wr = W2 + (size_t)row * H1;
        float s = 0.f;
#pragma unroll
        for (int i = 0; i < H1 / 32; i++)
            s += wr[lane + i * 32] * b1[lane + i * 32];
#pragma unroll
        for (int o = 16; o; o >>= 1) s += __shfl_xor_sync(~0u, s, o);
        if (lane == 0) g_t2[row] = s + b2[row];
    } else {
        int base = (bx - 672) * 4096;
        float4 z = make_float4(0.f, 0.f, 0.f, 0.f);
#pragma unroll
        for (int t = 0; t < 16; t++)
            ((float4*)g_t1)[base + tid + t * 256] = z;
    }
}

// ---------------------------------------------------------------------------
// K1 wchain (224 blocks, GEMM_SMEM dyn smem):
//   [0,64)   split-K(16) tf32 GEMM: T1 += Wf @ W2^T  (atomicAdd epilogue)
//   [64,96)  beff = Wf@t2 + bf
//   [96,224) bn x-scan second half (rows 32768..65535)
// ---------------------------------------------------------------------------
#define SMSTRIDE   36
#define ROWBYTES   (SMSTRIDE * 4)
#define A_BYTES    (128 * ROWBYTES)
#define B_BYTES    (256 * ROWBYTES)
#define STAGE_B    (A_BYTES + B_BYTES)
#define STAGES     3
#define GEMM_SMEM  (STAGES * STAGE_B)

__device__ __forceinline__ void issue_tile(const float* aPtr, const float* bPtr,
                                           uint32_t sA, uint32_t sB,
                                           int kOff, int K) {
#pragma unroll
    for (int j = 0; j < 4; j++)
        cp16(sA + j * 32 * ROWBYTES, aPtr + (size_t)j * 32 * K + kOff);
#pragma unroll
    for (int j = 0; j < 8; j++)
        cp16(sB + j * 32 * ROWBYTES, bPtr + (size_t)j * 32 * K + kOff);
}

__global__ __launch_bounds__(256, 1)
void wchain(const float* __restrict__ x, const float* __restrict__ Wf,
            const float* __restrict__ bf) {
    extern __shared__ char smem[];
    const int bx = blockIdx.x;
    const int tid = threadIdx.x;

    if (bx >= 96) {               // ---- bn x-scan, second half ----
        int part = (bx - 96) + 128;
        xscan_block(x, part, part * 256, tid);
        return;
    }
    if (bx >= 64) {               // ---- beff ----
        int w = tid >> 5, lane = tid & 31;
        int row = (bx - 64) * 8 + w;
        const float* wr = Wf + (size_t)row * H2;
        float s = 0.f;
#pragma unroll
        for (int i = 0; i < H2 / 32; i++)
            s += wr[lane + i * 32] * g_t2[lane + i * 32];
#pragma unroll
        for (int o = 16; o; o >>= 1) s += __shfl_xor_sync(~0u, s, o);
        if (lane == 0) g_beff[row] = s + bf[row];
        return;
    }

    // ---- split-K(16) GEMM: A=g_wfr [256,2048], W=g_w2t [512,2048], slice 128 ----
    const uint32_t sbase = smem_u32(smem);
    const int lane = tid & 31;
    const int g    = lane >> 2;
    const int tg   = lane & 3;
    const int wid  = tid >> 5;
    const int wm   = (wid & 1) * 64;
    const int wn   = (wid >> 1) * 64;

    const int xx = bx & 1, yy = (bx >> 1) & 1, z = bx >> 2;   // z: 0..15
    const int K = H2, kloop = 128, T = kloop >> 5;            // T = 4
    const float* A = g_wfr + z * kloop;
    const float* W = g_w2t + z * kloop;

    const size_t rowBase = (size_t)yy * 128;
    const size_t colBase = (size_t)xx * 256;

    const int r0 = tid >> 3;
    const int c0 = tid & 7;
    const float* aPtr = A + (rowBase + r0) * (size_t)K + c0 * 4;
    const float* bPtr = W + (colBase + r0) * (size_t)K + c0 * 4;
    const uint32_t sAo = r0 * ROWBYTES + c0 * 16;
    const uint32_t sBo = A_BYTES + r0 * ROWBYTES + c0 * 16;

    float acc[4][8][4];
#pragma unroll
    for (int mi = 0; mi < 4; mi++)
#pragma unroll
        for (int ni = 0; ni < 8; ni++)
#pragma unroll
            for (int k = 0; k < 4; k++) acc[mi][ni][k] = 0.f;

    issue_tile(aPtr, bPtr, sbase + sAo, sbase + sBo, 0, K);
    cp_commit();
    issue_tile(aPtr, bPtr, sbase + STAGE_B + sAo, sbase + STAGE_B + sBo, 32, K);
    cp_commit();

    for (int kt = 0; kt < T; kt++) {
        cp_wait<1>();
        __syncthreads();
        if (kt + 2 < T) {
            uint32_t sb2 = sbase + ((kt + 2) % STAGES) * STAGE_B;
            issue_tile(aPtr, bPtr, sb2 + sAo, sb2 + sBo, (kt + 2) * 32, K);
        }
        cp_commit();

        const unsigned* As = (const unsigned*)(smem + (kt % STAGES) * STAGE_B);
        const unsigned* Bs = (const unsigned*)(smem + (kt % STAGES) * STAGE_B + A_BYTES);
#pragma unroll
        for (int kk = 0; kk < 32; kk += 8) {
            unsigned a[4][4], b[8][2];
#pragma unroll
            for (int mi = 0; mi < 4; mi++) {
                int rr = wm + mi * 16;
                a[mi][0] = As[(rr + g)     * SMSTRIDE + kk + tg];
                a[mi][1] = As[(rr + g + 8) * SMSTRIDE + kk + tg];
                a[mi][2] = As[(rr + g)     * SMSTRIDE + kk + tg + 4];
                a[mi][3] = As[(rr + g + 8) * SMSTRIDE + kk + tg + 4];
            }
#pragma unroll
            for (int ni = 0; ni < 8; ni++) {
                int cc = wn + ni * 8 + g;
                b[ni][0] = Bs[cc * SMSTRIDE + kk + tg];
                b[ni][1] = Bs[cc * SMSTRIDE + kk + tg + 4];
            }
#pragma unroll
            for (int mi = 0; mi < 4; mi++)
#pragma unroll
                for (int ni = 0; ni < 8; ni++) {
                    asm volatile(
                        "mma.sync.aligned.m16n8k8.row.col.f32.tf32.tf32.f32 "
                        "{%0,%1,%2,%3}, {%4,%5,%6,%7}, {%8,%9}, {%0,%1,%2,%3};"
                        : "+f"(acc[mi][ni][0]), "+f"(acc[mi][ni][1]),
                          "+f"(acc[mi][ni][2]), "+f"(acc[mi][ni][3])
                        : "r"(a[mi][0]), "r"(a[mi][1]),
                          "r"(a[mi][2]), "r"(a[mi][3]),
                          "r"(b[ni][0]), "r"(b[ni][1]));
                }
        }
    }

#pragma unroll
    for (int mi = 0; mi < 4; mi++) {
        int row0 = (int)rowBase + wm + mi * 16 + g;
#pragma unroll
        for (int ni = 0; ni < 8; ni++) {
            int col = (int)colBase + wn + ni * 8 + 2 * tg;
            atomicAdd(&g_t1[row0 * H1 + col],           acc[mi][ni][0]);
            atomicAdd(&g_t1[row0 * H1 + col + 1],       acc[mi][ni][1]);
            atomicAdd(&g_t1[(row0 + 8) * H1 + col],     acc[mi][ni][2]);
            atomicAdd(&g_t1[(row0 + 8) * H1 + col + 1], acc[mi][ni][3]);
        }
    }
}

// ---------------------------------------------------------------------------
// K2 weff_k (72 blocks):
//   [0,64)  Weff = T1 @ W1 (fp32 FFMA 32x32 tiles, reg-prefetched) + round
//   [64,72) bn_final
// ---------------------------------------------------------------------------
__global__ __launch_bounds__(256)
void weff_k(const float* __restrict__ W1, const float* __restrict__ gamma,
            const float* __restrict__ beta) {
    int tid = threadIdx.x;
    if (blockIdx.x >= 64) {
        int c   = (blockIdx.x - 64) * 32 + (tid >> 3);
        int sub = tid & 7;
        float s = 0.f, q = 0.f;
#pragma unroll 8
        for (int b = sub; b < 256; b += 8) {
            s += g_partS[b * 256 + c];
            q += g_partQ[b * 256 + c];
        }
#pragma unroll
        for (int o = 4; o; o >>= 1) {
            s += __shfl_xor_sync(~0u, s, o);
            q += __shfl_xor_sync(~0u, q, o);
        }
        if (sub == 0) {
            const float inv = 1.0f / (float)NROWS;
            float mu  = s * inv;
            float var = q * inv - mu * mu;
            float sc  = gamma[c] * rsqrtf(var + 1e-5f);
            g_scale[c] = sc;
            g_shift[c] = beta[c] - mu * sc;
        }
        return;
    }
    __shared__ float As[32][36], Bs[32][36];
    int i0 = (blockIdx.x >> 3) * 32, j0 = (blockIdx.x & 7) * 32;
    int ty = tid >> 4, tx = tid & 15;
    int lr = tid >> 3, lc4 = (tid & 7) * 4;
    float a00 = 0.f, a01 = 0.f, a10 = 0.f, a11 = 0.f;

    float4 ra = *(const float4*)(&g_t1[(i0 + lr) * H1 + lc4]);
    float4 rb = *(const float4*)(&W1[(size_t)lr * DIM + j0 + lc4]);

    for (int kb = 0; kb < H1; kb += 32) {
        *(float4*)(&As[lr][lc4]) = ra;
        *(float4*)(&Bs[lr][lc4]) = rb;
        __syncthreads();
        if (kb + 32 < H1) {
            ra = *(const float4*)(&g_t1[(i0 + lr) * H1 + kb + 32 + lc4]);
            rb = *(const float4*)(&W1[(size_t)(kb + 32 + lr) * DIM + j0 + lc4]);
        }
#pragma unroll
        for (int k = 0; k < 32; k++) {
            float x0 = As[ty * 2][k],     x1 = As[ty * 2 + 1][k];
            float y0 = Bs[k][tx * 2],     y1 = Bs[k][tx * 2 + 1];
            a00 = fmaf(x0, y0, a00); a01 = fmaf(x0, y1, a01);
            a10 = fmaf(x1, y0, a10); a11 = fmaf(x1, y1, a11);
        }
        __syncthreads();
    }
    int r0 = i0 + ty * 2, c0 = j0 + tx * 2;
    g_weff[r0 * DIM + c0]           = __uint_as_float(f2tf(a00));
    g_weff[r0 * DIM + c0 + 1]       = __uint_as_float(f2tf(a01));
    g_weff[(r0 + 1) * DIM + c0]     = __uint_as_float(f2tf(a10));
    g_weff[(r0 + 1) * DIM + c0 + 1] = __uint_as_float(f2tf(a11));
}

// ---------------------------------------------------------------------------
// K3 fused final: 128x128 CTA tile, 128 threads (4 warps of 64x64), 2 CTAs/SM.
// A double-buffered (generated in-kernel), B double-buffered (cp.async).
// grid (2, 512): blockIdx.x = column half; col-half 0 also writes raw.
// smem: A[2][18432] | B[2][18432] = 73728 B.
// ---------------------------------------------------------------------------
#define FA_STAGE 18432
#define FB_OFF   (2 * FA_STAGE)
#define F_SMEM   (4 * FA_STAGE)        // 73728

__device__ __forceinline__ void issueB_f(uint32_t sbase, int slot, int kt,
                                         int tid, int colBase) {
#pragma unroll
    for (int j = 0; j < 8; j++) {
        int r = (tid >> 3) + j * 16;
        cp16(sbase + FB_OFF + slot * FA_STAGE + r * ROWBYTES + (tid & 7) * 16,
             g_weff + (colBase + r) * 256 + kt * 32 + (tid & 7) * 4);
    }
}

__global__ __launch_bounds__(128, 2)
void fused_final(const float* __restrict__ x, float* __restrict__ raw,
                 float* __restrict__ out) {
    extern __shared__ char smem[];
    const uint32_t sbase = smem_u32(smem);
    const int tid  = threadIdx.x;
    const int lane = tid & 31;
    const int g    = lane >> 2;
    const int tg   = lane & 3;
    const int wid  = tid >> 5;            // 0..3
    const int wm   = (wid & 1) * 64;
    const int wn   = (wid >> 1) * 64;
    const int colBase = blockIdx.x * 128;
    const bool doRaw  = (blockIdx.x == 0);
    const size_t rowBase = (size_t)blockIdx.y * 128;

    issueB_f(sbase, 0, 0, tid, colBase);
    cp_commit();
    issueB_f(sbase, 1, 1, tid, colBase);
    cp_commit();

    // A-gen geometry: thread covers 8 rows (r = tid>>3 + 16j), fixed f4 col cf
    const int cf = tid & 7;
    const int ar0 = tid >> 3;             // 0..15
    const float* xp0 = x   + (rowBase + ar0) * 256 + cf * 4;
    float*       rp0 = raw + (rowBase + ar0) * 256 + cf * 4;
    const uint32_t so0 = ar0 * ROWBYTES + cf * 16;

    // generate chunk 0 into A slot 0
    float4 nv[8];
#pragma unroll
    for (int j = 0; j < 8; j++) nv[j] = *(const float4*)(xp0 + j * 4096);
    {
        float4 sc = ((const float4*)g_scale)[cf];
        float4 sh = ((const float4*)g_shift)[cf];
#pragma unroll
        for (int j = 0; j < 8; j++) {
            float4 xn;
            xn.x = fmaf(nv[j].x, sc.x, sh.x);
            xn.y = fmaf(nv[j].y, sc.y, sh.y);
            xn.z = fmaf(nv[j].z, sc.z, sh.z);
            xn.w = fmaf(nv[j].w, sc.w, sh.w);
            if (doRaw) {
                float4 t;
                t.x = tanh_ap(xn.x); t.y = tanh_ap(xn.y);
                t.z = tanh_ap(xn.z); t.w = tanh_ap(xn.w);
                *(float4*)(rp0 + j * 4096) = t;
            }
            uint4 rb;
            rb.x = f2tf(xn.x); rb.y = f2tf(xn.y);
            rb.z = f2tf(xn.z); rb.w = f2tf(xn.w);
            *(uint4*)(smem + so0 + j * 16 * ROWBYTES) = rb;
        }
    }

    float acc[4][8][4];
#pragma unroll
    for (int mi = 0; mi < 4; mi++)
#pragma unroll
        for (int ni = 0; ni < 8; ni++)
#pragma unroll
            for (int k = 0; k < 4; k++) acc[mi][ni][k] = 0.f;

    for (int kt = 0; kt < 8; kt++) {
        if (kt < 7) {
#pragma unroll
            for (int j = 0; j < 8; j++)
                nv[j] = *(const float4*)(xp0 + j * 4096 + (kt + 1) * 32);
        }
        cp_wait<1>();
        __syncthreads();

        const unsigned* As = (const unsigned*)(smem + (kt & 1) * FA_STAGE);
        const unsigned* Bs = (const unsigned*)(smem + FB_OFF + (kt & 1) * FA_STAGE);
#pragma unroll
        for (int kk = 0; kk < 32; kk += 8) {
            unsigned a[4][4], b[8][2];
#pragma unroll
            for (int mi = 0; mi < 4; mi++) {
                int rr = wm + mi * 16;
                a[mi][0] = As[(rr + g)     * SMSTRIDE + kk + tg];
                a[mi][1] = As[(rr + g + 8) * SMSTRIDE + kk + tg];
                a[mi][2] = As[(rr + g)     * SMSTRIDE + kk + tg + 4];
                a[mi][3] = As[(rr + g + 8) * SMSTRIDE + kk + tg + 4];
            }
#pragma unroll
            for (int ni = 0; ni < 8; ni++) {
                int cc = wn + ni * 8 + g;
                b[ni][0] = Bs[cc * SMSTRIDE + kk + tg];
                b[ni][1] = Bs[cc * SMSTRIDE + kk + tg + 4];
            }
#pragma unroll
            for (int mi = 0; mi < 4; mi++)
#pragma unroll
                for (int ni = 0; ni < 8; ni++) {
                    asm volatile(
                        "mma.sync.aligned.m16n8k8.row.col.f32.tf32.tf32.f32 "
                        "{%0,%1,%2,%3}, {%4,%5,%6,%7}, {%8,%9}, {%0,%1,%2,%3};"
                        : "+f"(acc[mi][ni][0]), "+f"(acc[mi][ni][1]),
                          "+f"(acc[mi][ni][2]), "+f"(acc[mi][ni][3])
                        : "r"(a[mi][0]), "r"(a[mi][1]),
                          "r"(a[mi][2]), "r"(a[mi][3]),
                          "r"(b[ni][0]), "r"(b[ni][1]));
                }
        }

        // generate chunk kt+1 into A slot (kt+1)&1
        if (kt < 7) {
            float4 sc = ((const float4*)g_scale)[(kt + 1) * 8 + cf];
            float4 sh = ((const float4*)g_shift)[(kt + 1) * 8 + cf];
#pragma unroll
            for (int j = 0; j < 8; j++) {
                float4 xn;
                xn.x = fmaf(nv[j].x, sc.x, sh.x);
                xn.y = fmaf(nv[j].y, sc.y, sh.y);
                xn.z = fmaf(nv[j].z, sc.z, sh.z);
                xn.w = fmaf(nv[j].w, sc.w, sh.w);
                if (doRaw) {
                    float4 t;
                    t.x = tanh_ap(xn.x); t.y = tanh_ap(xn.y);
                    t.z = tanh_ap(xn.z); t.w = tanh_ap(xn.w);
                    *(float4*)(rp0 + j * 4096 + (kt + 1) * 32) = t;
                }
                uint4 rb;
                rb.x = f2tf(xn.x); rb.y = f2tf(xn.y);
                rb.z = f2tf(xn.z); rb.w = f2tf(xn.w);
                *(uint4*)(smem + ((kt + 1) & 1) * FA_STAGE + so0 +
                          j * 16 * ROWBYTES) = rb;
            }
        }
        __syncthreads();               // all warps done reading B slot kt&1
        if (kt + 2 < 8) issueB_f(sbase, kt & 1, kt + 2, tid, colBase);
        cp_commit();
    }

    // epilogue: + beff, tanh, store
#pragma unroll
    for (int mi = 0; mi < 4; mi++) {
        size_t row0 = rowBase + wm + mi * 16 + g;
#pragma unroll
        for (int ni = 0; ni < 8; ni++) {
            int col = colBase + wn + ni * 8 + 2 * tg;
            float v0 = tanh_ap(acc[mi][ni][0] + g_beff[col]);
            float v1 = tanh_ap(acc[mi][ni][1] + g_beff[col + 1]);
            float v2 = tanh_ap(acc[mi][ni][2] + g_beff[col]);
            float v3 = tanh_ap(acc[mi][ni][3] + g_beff[col + 1]);
            *(float2*)&out[row0 * 256 + col]       = make_float2(v0, v1);
            *(float2*)&out[(row0 + 8) * 256 + col] = make_float2(v2, v3);
        }
    }
}

// ---------------------------------------------------------------------------
// Launch (4 kernels)
// ---------------------------------------------------------------------------
extern "C" void kernel_launch(void* const* d_in, const int* in_sizes, int n_in,
                              void* d_out, int out_size) {
    const float* x     = (const float*)d_in[0];
    const float* gamma = (const float*)d_in[1];
    const float* beta  = (const float*)d_in[2];
    const float* W1    = (const float*)d_in[3];
    const float* b1    = (const float*)d_in[4];
    const float* W2    = (const float*)d_in[5];
    const float* b2    = (const float*)d_in[6];
    const float* Wf    = (const float*)d_in[7];
    const float* bf    = (const float*)d_in[8];

    float* out = (float*)d_out;
    float* raw = out + (size_t)NROWS * DIM;

    cudaFuncSetAttribute(wchain,
                         cudaFuncAttributeMaxDynamicSharedMemorySize, GEMM_SMEM);
    cudaFuncSetAttribute(fused_final,
                         cudaFuncAttributeMaxDynamicSharedMemorySize, F_SMEM);

    prep<<<680, 256>>>(x, W2, Wf, b1, b2);
    wchain<<<224, 256, GEMM_SMEM>>>(x, Wf, bf);
    weff_k<<<72, 256>>>(W1, gamma, beta);
    fused_final<<<dim3(2, NROWS / 128), 128, F_SMEM>>>(x, raw, out);
}